// round 2
// baseline (speedup 1.0000x reference)
#include <cuda_runtime.h>
#include <math.h>
#include <float.h>

// Problem constants (fixed shapes)
#define B_    4
#define Q_    75
#define BQ_   300          // B_*Q_
#define C_    640
#define M_    100          // h*w
#define J_    25           // n_way*k_shot
#define NW_   5
#define MS_   500          // K_SHOT*h*w
#define COLS_ 2500         // NW_*MS_  == J_*M_
#define NT_   64           // n-tile
#define KC_   16           // k-chunk
#define NTILES_ ((COLS_ + NT_ - 1) / NT_)   // 40
#define EPS_  1e-8f
#define TEMP_ 2.0f

// Scratch (static device globals; no allocation)
__device__ float g_qinv[BQ_ * M_];      // 30000
__device__ float g_sinv[B_ * COLS_];    // 10000
__device__ float g_pred[BQ_ * NW_];     // 1500

// ---------------------------------------------------------------------------
// Inverse-norm kernels. Descriptor (.., c, m) has stride 100 over c; thread
// t = m gives coalesced loads at each c step.
// ---------------------------------------------------------------------------
__global__ void qnorm_k(const float* __restrict__ q) {
    int bq = blockIdx.x;
    int t = threadIdx.x;
    if (t >= M_) return;
    const float* p = q + (size_t)bq * (C_ * M_) + t;
    float ss = 0.f;
#pragma unroll 8
    for (int c = 0; c < C_; c++) {
        float v = p[(size_t)c * M_];
        ss = fmaf(v, v, ss);
    }
    g_qinv[bq * M_ + t] = 1.0f / (sqrtf(ss) + EPS_);
}

__global__ void snorm_k(const float* __restrict__ s) {
    int bj = blockIdx.x;        // b*25 + j
    int t = threadIdx.x;
    if (t >= M_) return;
    const float* p = s + (size_t)bj * (C_ * M_) + t;
    float ss = 0.f;
#pragma unroll 8
    for (int c = 0; c < C_; c++) {
        float v = p[(size_t)c * M_];
        ss = fmaf(v, v, ss);
    }
    int b = bj / J_, j = bj % J_;
    g_sinv[b * COLS_ + j * M_ + t] = 1.0f / (sqrtf(ss) + EPS_);
}

// ---------------------------------------------------------------------------
// Main kernel: one CTA per (b,q). GEMM 100x2500 (K=640) in 64-col tiles with
// fused per-m reductions, then mutual-nearest mask + per-class logit sums.
// ---------------------------------------------------------------------------
__global__ __launch_bounds__(256) void dmn4_main_k(
    const float* __restrict__ sup,   // [B_, J_, C_, M_]
    const float* __restrict__ qry,   // [B_, Q_, C_, M_]
    float* __restrict__ pred)        // [BQ_, NW_]
{
    __shared__ float smQ[KC_][M_];       // 6400 B
    __shared__ float smS[KC_][NT_];      // 4096 B
    __shared__ float smT[M_][NT_ + 1];   // 26000 B (padded: conflict-free col reads)
    __shared__ float smSinv[NT_];
    __shared__ int   smNear[M_];
    __shared__ float smDiff[M_];
    __shared__ float smCmax[M_][NW_];
    __shared__ float smMask[M_];

    const int bq = blockIdx.x;
    const int b  = bq / Q_;
    const int tid = threadIdx.x;
    const int tx = tid & 15;     // n sub-tile (4 cols each)
    const int ty = tid >> 4;     // m stride-16 set
    const int nm = (ty < 4) ? 7 : 6;   // #m rows this thread owns (uniform per warp)

    const size_t qbase = (size_t)bq * (C_ * M_);

    // Per-m stats (only meaningful for tid < 100 in epilogue role)
    float cmax[NW_];
    float gval = -FLT_MAX;
    int   gidx = 0;
#pragma unroll
    for (int w = 0; w < NW_; w++) cmax[w] = -FLT_MAX;
    float qiv = (tid < M_) ? g_qinv[bq * M_ + tid] : 0.f;

    for (int nt = 0; nt < NTILES_; nt++) {
        const int col0 = nt * NT_;
        float acc[7][4];
#pragma unroll
        for (int i = 0; i < 7; i++)
#pragma unroll
            for (int jn = 0; jn < 4; jn++) acc[i][jn] = 0.f;

        for (int k0 = 0; k0 < C_; k0 += KC_) {
            // stage query chunk [KC_ x 100]
            for (int idx = tid; idx < KC_ * M_; idx += 256) {
                int kk = idx / M_, mm = idx % M_;
                smQ[kk][mm] = qry[qbase + (size_t)(k0 + kk) * M_ + mm];
            }
            // stage support chunk [KC_ x 64]
            for (int idx = tid; idx < KC_ * NT_; idx += 256) {
                int kk = idx / NT_, nl = idx % NT_;
                int col = col0 + nl;
                float v = 0.f;
                if (col < COLS_) {
                    int j = col / M_, ms = col % M_;
                    v = sup[((size_t)(b * J_ + j) * C_ + (k0 + kk)) * M_ + ms];
                }
                smS[kk][nl] = v;
            }
            __syncthreads();

#pragma unroll
            for (int kk = 0; kk < KC_; kk++) {
                float4 sv = *(const float4*)&smS[kk][tx * 4];
#pragma unroll
                for (int i = 0; i < 7; i++) {
                    if (i < nm) {
                        float qv = smQ[kk][ty + 16 * i];
                        acc[i][0] = fmaf(qv, sv.x, acc[i][0]);
                        acc[i][1] = fmaf(qv, sv.y, acc[i][1]);
                        acc[i][2] = fmaf(qv, sv.z, acc[i][2]);
                        acc[i][3] = fmaf(qv, sv.w, acc[i][3]);
                    }
                }
            }
            __syncthreads();
        }

        // write raw dot tile + stage sinv
#pragma unroll
        for (int i = 0; i < 7; i++) {
            if (i < nm) {
                int m = ty + 16 * i;
#pragma unroll
                for (int jn = 0; jn < 4; jn++)
                    smT[m][tx * 4 + jn] = acc[i][jn];
            }
        }
        if (tid < NT_) {
            int col = col0 + tid;
            smSinv[tid] = (col < COLS_) ? g_sinv[b * COLS_ + col] : 0.f;
        }
        __syncthreads();

        // fused reduction: thread t = m scans its row
        if (tid < M_) {
            int lim = COLS_ - col0;
            if (lim > NT_) lim = NT_;
            for (int nl = 0; nl < lim; nl++) {
                float sv = smT[tid][nl] * qiv * smSinv[nl];
                int col = col0 + nl;
                int w = col / MS_;
                if (sv > cmax[w]) cmax[w] = sv;
                if (sv > gval) { gval = sv; gidx = col; }   // strict > = first-index argmax
            }
        }
        __syncthreads();
    }

    // top-2 over class maxes; publish per-m stats
    if (tid < M_) {
        float m1 = -FLT_MAX, m2 = -FLT_MAX;
#pragma unroll
        for (int w = 0; w < NW_; w++) {
            float v = cmax[w];
            if (v > m1) { m2 = m1; m1 = v; }
            else if (v > m2) { m2 = v; }
        }
        smDiff[tid] = m1 - m2;
        smNear[tid] = gidx;
#pragma unroll
        for (int w = 0; w < NW_; w++) smCmax[tid][w] = cmax[w];
    }
    __syncthreads();

    // mutual-nearest: m kept iff m == argmax_{m'} diffs_m[m', slot_m]
    // (non-mappers contribute 0; first-index tie-break; empty column -> idx 0)
    if (tid < M_) {
        int slot = smNear[tid];
        float best = -1.0f;
        int idx = -1;
        for (int mp = 0; mp < M_; mp++) {
            float v = (smNear[mp] == slot) ? smDiff[mp] : 0.0f;
            if (v > best) { best = v; idx = mp; }
        }
        smMask[tid] = (idx == tid) ? TEMP_ : 0.0f;
    }
    __syncthreads();

    // predict[bq][w] = sum_m S_max[w][m] * mask[m]   (deterministic order)
    if (tid < NW_) {
        float p = 0.f;
        for (int m = 0; m < M_; m++)
            p += smCmax[m][tid] * smMask[m];
        pred[bq * NW_ + tid] = p;
    }
}

// ---------------------------------------------------------------------------
// Final loss: log-softmax NLL, deterministic tree reduction.
// ---------------------------------------------------------------------------
__global__ void loss_k(const float* __restrict__ pred,
                       const int* __restrict__ qy,
                       float* __restrict__ out)
{
    __shared__ float part[512];
    int t = threadIdx.x;
    float v = 0.f;
    if (t < BQ_) {
        const float* p = pred + t * NW_;
        float mx = p[0];
#pragma unroll
        for (int w = 1; w < NW_; w++) mx = fmaxf(mx, p[w]);
        float se = 0.f;
#pragma unroll
        for (int w = 0; w < NW_; w++) se += expf(p[w] - mx);
        float lse = mx + logf(se);
        int y = qy[t];
        v = p[y] - lse;
    }
    part[t] = v;
    __syncthreads();
    for (int s = 256; s > 0; s >>= 1) {
        if (t < s) part[t] += part[t + s];
        __syncthreads();
    }
    if (t == 0) out[0] = -part[0] / (float)BQ_;
}

// ---------------------------------------------------------------------------
extern "C" void kernel_launch(void* const* d_in, const int* in_sizes, int n_in,
                              void* d_out, int out_size)
{
    const float* support_xf = (const float*)d_in[0];   // [4,25,640,100]
    // d_in[1] = support_y (unused by reference)
    const float* query_xf   = (const float*)d_in[2];   // [4,75,640,100]
    const int*   query_y    = (const int*)d_in[3];     // [4,75]
    float* out = (float*)d_out;

    float* qinv; cudaGetSymbolAddress((void**)&qinv, g_qinv);
    float* sinv; cudaGetSymbolAddress((void**)&sinv, g_sinv);
    float* pred; cudaGetSymbolAddress((void**)&pred, g_pred);
    (void)qinv; (void)sinv;

    qnorm_k<<<BQ_, 128>>>(query_xf);
    snorm_k<<<B_ * J_, 128>>>(support_xf);
    dmn4_main_k<<<BQ_, 256>>>(support_xf, query_xf, pred);
    loss_k<<<1, 512>>>(pred, query_y, out);
}

// round 4
// speedup vs baseline: 1.3450x; 1.3450x over previous
#include <cuda_runtime.h>
#include <math.h>
#include <float.h>

typedef unsigned long long ull;

// Problem constants (fixed shapes)
#define B_    4
#define Q_    75
#define BQ_   300          // B_*Q_
#define C_    640
#define M_    100          // h*w
#define J_    25           // n_way*k_shot
#define NW_   5
#define MS_   500          // K_SHOT*h*w
#define COLS_ 2500         // NW_*MS_
#define NT_   64           // n-tile
#define KC_   16           // k-chunk
#define NCH_  (C_ / KC_)                    // 40 chunks
#define NTILES_ ((COLS_ + NT_ - 1) / NT_)   // 40
#define EPS_  1e-8f
#define TEMP_ 2.0f

// Scratch (static device globals; no allocation)
__device__ float g_qinv[BQ_ * M_];
__device__ float g_sinv[B_ * COLS_];
__device__ float g_pred[BQ_ * NW_];

__device__ __forceinline__ void fma2(ull& d, ull a, ull b) {
    asm("fma.rn.f32x2 %0, %1, %2, %0;" : "+l"(d) : "l"(a), "l"(b));
}
__device__ __forceinline__ void unpack2(float& lo, float& hi, ull a) {
    asm("mov.b64 {%0, %1}, %2;" : "=f"(lo), "=f"(hi) : "l"(a));
}

// ---------------------------------------------------------------------------
// Inverse-norm kernels (coalesced over m at each c step).
// ---------------------------------------------------------------------------
__global__ void qnorm_k(const float* __restrict__ q) {
    int bq = blockIdx.x;
    int t = threadIdx.x;
    if (t >= M_) return;
    const float* p = q + (size_t)bq * (C_ * M_) + t;
    float ss = 0.f;
#pragma unroll 8
    for (int c = 0; c < C_; c++) { float v = p[(size_t)c * M_]; ss = fmaf(v, v, ss); }
    g_qinv[bq * M_ + t] = 1.0f / (sqrtf(ss) + EPS_);
}

__global__ void snorm_k(const float* __restrict__ s) {
    int bj = blockIdx.x;
    int t = threadIdx.x;
    if (t >= M_) return;
    const float* p = s + (size_t)bj * (C_ * M_) + t;
    float ss = 0.f;
#pragma unroll 8
    for (int c = 0; c < C_; c++) { float v = p[(size_t)c * M_]; ss = fmaf(v, v, ss); }
    int b = bj / J_, j = bj % J_;
    g_sinv[b * COLS_ + j * M_ + t] = 1.0f / (sqrtf(ss) + EPS_);
}

// ---------------------------------------------------------------------------
// Main kernel: one CTA per (b,q). 100x2500 GEMM (K=640) with f32x2 FMAs,
// register-prefetch double buffering, fused max/argmax epilogue.
// ---------------------------------------------------------------------------
__global__ __launch_bounds__(256, 3) void dmn4_main_k(
    const float* __restrict__ sup,   // [B_, J_, C_, M_]
    const float* __restrict__ qry,   // [B_, Q_, C_, M_]
    float* __restrict__ pred)        // [BQ_, NW_]
{
    // Double-buffered stages
    __shared__ __align__(16) float2 smQ2[2][KC_ * M_];  // 25600 B (dup pairs)
    __shared__ __align__(16) float  smS [2][KC_ * NT_]; //  8192 B
    __shared__ float  smSinv[NT_];                      //   256 B
    __shared__ float  smPV[M_][16];                     //  6400 B
    __shared__ unsigned short smPI[M_][16];             //  3200 B
    __shared__ int    smNear[M_];
    __shared__ float  smDiff[M_];
    __shared__ float  smCmax[M_][NW_];
    __shared__ float  smMask[M_];

    const int bq = blockIdx.x;
    const int b  = bq / Q_;
    const int tid = threadIdx.x;
    const int tx = tid & 15;     // 4 cols per tx
    const int ty = tid >> 4;     // m row base
    const int nm = (ty < 4) ? 7 : 6;
    const size_t qbase = (size_t)bq * (C_ * M_);

    // Per-m stats held by thread tid<100 (reducer role)
    float cmax[NW_];
    float gval = -FLT_MAX;
    int   gidx = 0;
#pragma unroll
    for (int w = 0; w < NW_; w++) cmax[w] = -FLT_MAX;

    // qinv for this thread's GEMM rows
    float qiv[7];
#pragma unroll
    for (int i = 0; i < 7; i++) {
        int m = ty + 16 * i;
        qiv[i] = (m < M_) ? g_qinv[bq * M_ + m] : 0.f;
    }

    // q staging element indices: e = tid + 256*j, j<7 (valid while e<1600)
    // s staging: e = tid + 256*t, t<4, kk=e>>6, nl=e&63

    for (int nt = 0; nt < NTILES_; nt++) {
        const int col0 = nt * NT_;

        // stage sinv for this tile
        if (tid < NT_) {
            int col = col0 + tid;
            smSinv[tid] = (col < COLS_) ? g_sinv[b * COLS_ + col] : 0.f;
        }

        // per-tile support base addresses (k0-invariant part)
        size_t sbase[4];
        bool   svalid[4];
#pragma unroll
        for (int t = 0; t < 4; t++) {
            int e = tid + 256 * t;
            int kk = e >> 6, nl = e & 63;
            int col = col0 + nl;
            svalid[t] = (col < COLS_);
            int cc = svalid[t] ? col : 0;
            int j = cc / M_, ms = cc % M_;
            sbase[t] = ((size_t)(b * J_ + j) * C_ + kk) * M_ + ms;
        }

        // accumulators: acc[i][p] = f32x2 over cols (4tx+2p, 4tx+2p+1)
        ull acc[7][2];
#pragma unroll
        for (int i = 0; i < 7; i++) { acc[i][0] = 0ull; acc[i][1] = 0ull; }

        // ---- prefetch chunk 0 ----
        float qr[7], sr[4];
#pragma unroll
        for (int j = 0; j < 7; j++) {
            int e = tid + 256 * j;
            qr[j] = (e < KC_ * M_) ? qry[qbase + e] : 0.f;
        }
#pragma unroll
        for (int t = 0; t < 4; t++)
            sr[t] = svalid[t] ? sup[sbase[t]] : 0.f;

        // store chunk 0 into buf 0
#pragma unroll
        for (int j = 0; j < 7; j++) {
            int e = tid + 256 * j;
            if (e < KC_ * M_) smQ2[0][e] = make_float2(qr[j], qr[j]);
        }
#pragma unroll
        for (int t = 0; t < 4; t++) smS[0][tid + 256 * t] = sr[t];
        __syncthreads();

        int buf = 0;
        for (int c = 0; c < NCH_; c++) {
            // prefetch next chunk
            if (c < NCH_ - 1) {
                const int koff = (c + 1) * KC_ * M_;   // = k0*100
#pragma unroll
                for (int j = 0; j < 7; j++) {
                    int e = tid + 256 * j;
                    if (e < KC_ * M_) qr[j] = qry[qbase + koff + e];
                }
#pragma unroll
                for (int t = 0; t < 4; t++)
                    sr[t] = svalid[t] ? sup[sbase[t] + koff] : 0.f;
            }

            // compute on current buffer
            {
                const ull* q2 = (const ull*)smQ2[buf];
                const ull* s2 = (const ull*)smS[buf];
#pragma unroll
                for (int kk = 0; kk < KC_; kk++) {
                    ulonglong2 sv = *(const ulonglong2*)&s2[kk * 32 + tx * 2];
#pragma unroll
                    for (int i = 0; i < 7; i++) {
                        if (i < nm) {
                            ull qv = q2[kk * M_ + ty + 16 * i];
                            fma2(acc[i][0], qv, sv.x);
                            fma2(acc[i][1], qv, sv.y);
                        }
                    }
                }
            }

            if (c < NCH_ - 1) {
                int nb = buf ^ 1;
#pragma unroll
                for (int j = 0; j < 7; j++) {
                    int e = tid + 256 * j;
                    if (e < KC_ * M_) smQ2[nb][e] = make_float2(qr[j], qr[j]);
                }
#pragma unroll
                for (int t = 0; t < 4; t++) smS[nb][tid + 256 * t] = sr[t];
                __syncthreads();
                buf = nb;
            }
        }

        // ---- epilogue: per-thread 4-col max/argmax, write (val,idx) pairs ----
        {
            float4 sv4 = *(const float4*)&smSinv[tx * 4];
            const int cb = col0 + tx * 4;
#pragma unroll
            for (int i = 0; i < 7; i++) {
                if (i < nm) {
                    int m = ty + 16 * i;
                    float best = -FLT_MAX;
                    int bidx = 0;
                    if (cb < COLS_) {
                        float a0, a1, a2, a3;
                        unpack2(a0, a1, acc[i][0]);
                        unpack2(a2, a3, acc[i][1]);
                        float v0 = a0 * qiv[i] * sv4.x;
                        float v1 = a1 * qiv[i] * sv4.y;
                        float v2 = a2 * qiv[i] * sv4.z;
                        float v3 = a3 * qiv[i] * sv4.w;
                        best = v0; bidx = cb;
                        if (v1 > best) { best = v1; bidx = cb + 1; }
                        if (v2 > best) { best = v2; bidx = cb + 2; }
                        if (v3 > best) { best = v3; bidx = cb + 3; }
                    }
                    smPV[m][tx] = best;
                    smPI[m][tx] = (unsigned short)bidx;
                }
            }
        }
        __syncthreads();

        // reducer: thread m scans 16 pairs in ascending column order
        if (tid < M_) {
#pragma unroll
            for (int e = 0; e < 16; e++) {
                float v = smPV[tid][e];
                int idx = smPI[tid][e];
                int w = idx / MS_;
                if (v > cmax[w]) cmax[w] = v;
                if (v > gval) { gval = v; gidx = idx; }   // first-index ties
            }
        }
        __syncthreads();
    }

    // top-2 over class maxes; publish per-m stats
    if (tid < M_) {
        float m1 = -FLT_MAX, m2 = -FLT_MAX;
#pragma unroll
        for (int w = 0; w < NW_; w++) {
            float v = cmax[w];
            if (v > m1) { m2 = m1; m1 = v; }
            else if (v > m2) { m2 = v; }
        }
        smDiff[tid] = m1 - m2;
        smNear[tid] = gidx;
#pragma unroll
        for (int w = 0; w < NW_; w++) smCmax[tid][w] = cmax[w];
    }
    __syncthreads();

    // mutual-nearest: m kept iff m == argmax_{m'} (near[m']==slot ? diff[m'] : 0)
    if (tid < M_) {
        int slot = smNear[tid];
        float best = -1.0f;
        int idx = -1;
        for (int mp = 0; mp < M_; mp++) {
            float v = (smNear[mp] == slot) ? smDiff[mp] : 0.0f;
            if (v > best) { best = v; idx = mp; }
        }
        smMask[tid] = (idx == tid) ? TEMP_ : 0.0f;
    }
    __syncthreads();

    if (tid < NW_) {
        float p = 0.f;
        for (int m = 0; m < M_; m++)
            p += smCmax[m][tid] * smMask[m];
        pred[bq * NW_ + tid] = p;
    }
}

// ---------------------------------------------------------------------------
// Final loss: log-softmax NLL, deterministic tree reduction.
// ---------------------------------------------------------------------------
__global__ void loss_k(const float* __restrict__ pred,
                       const int* __restrict__ qy,
                       float* __restrict__ out)
{
    __shared__ float part[512];
    int t = threadIdx.x;
    float v = 0.f;
    if (t < BQ_) {
        const float* p = pred + t * NW_;
        float mx = p[0];
#pragma unroll
        for (int w = 1; w < NW_; w++) mx = fmaxf(mx, p[w]);
        float se = 0.f;
#pragma unroll
        for (int w = 0; w < NW_; w++) se += expf(p[w] - mx);
        float lse = mx + logf(se);
        int y = qy[t];
        v = p[y] - lse;
    }
    part[t] = v;
    __syncthreads();
    for (int s = 256; s > 0; s >>= 1) {
        if (t < s) part[t] += part[t + s];
        __syncthreads();
    }
    if (t == 0) out[0] = -part[0] / (float)BQ_;
}

// ---------------------------------------------------------------------------
extern "C" void kernel_launch(void* const* d_in, const int* in_sizes, int n_in,
                              void* d_out, int out_size)
{
    const float* support_xf = (const float*)d_in[0];   // [4,25,640,100]
    const float* query_xf   = (const float*)d_in[2];   // [4,75,640,100]
    const int*   query_y    = (const int*)d_in[3];     // [4,75]
    float* out = (float*)d_out;

    float* pred; cudaGetSymbolAddress((void**)&pred, g_pred);

    qnorm_k<<<BQ_, 128>>>(query_xf);
    snorm_k<<<B_ * J_, 128>>>(support_xf);
    dmn4_main_k<<<BQ_, 256>>>(support_xf, query_xf, pred);
    loss_k<<<1, 512>>>(pred, query_y, out);
}

// round 5
// speedup vs baseline: 1.8172x; 1.3511x over previous
#include <cuda_runtime.h>
#include <math.h>
#include <float.h>

typedef unsigned long long ull;

// Problem constants (fixed shapes)
#define B_    4
#define Q_    75
#define BQ_   300          // B_*Q_
#define C_    640
#define M_    100          // h*w
#define J_    25           // n_way*k_shot
#define NW_   5
#define MS_   500          // K_SHOT*h*w
#define COLS_ 2500         // NW_*MS_
#define NT_   64           // n-tile
#define KC_   16           // k-chunk
#define NCH_  (C_ / KC_)                    // 40
#define NTILES_ ((COLS_ + NT_ - 1) / NT_)   // 40
#define QSTR_ 18           // padded k-stride (floats) for transposed tiles
#define EPS_  1e-8f
#define TEMP_ 2.0f

// Scratch (static device globals; no allocation)
__device__ float g_qinv[BQ_ * M_];
__device__ float g_sinv[B_ * COLS_];
__device__ float g_pred[BQ_ * NW_];

__device__ __forceinline__ void fma2(ull& d, ull a, ull b) {
    asm("fma.rn.f32x2 %0, %1, %2, %0;" : "+l"(d) : "l"(a), "l"(b));
}
__device__ __forceinline__ void unpack2(float& lo, float& hi, ull a) {
    asm("mov.b64 {%0, %1}, %2;" : "=f"(lo), "=f"(hi) : "l"(a));
}
__device__ __forceinline__ void cpa4(unsigned dst, const float* src, int srcsz) {
    // 4-byte async copy; srcsz=0 -> zero-fill
    asm volatile("cp.async.ca.shared.global [%0], [%1], 4, %2;"
                 :: "r"(dst), "l"(src), "r"(srcsz));
}
__device__ __forceinline__ void cpa4u(unsigned dst, const float* src) {
    asm volatile("cp.async.ca.shared.global [%0], [%1], 4;"
                 :: "r"(dst), "l"(src));
}
#define CP_COMMIT() asm volatile("cp.async.commit_group;")
#define CP_WAIT0()  asm volatile("cp.async.wait_group 0;")

// ---------------------------------------------------------------------------
// Inverse-norm kernels (coalesced over m at each c step).
// ---------------------------------------------------------------------------
__global__ void qnorm_k(const float* __restrict__ q) {
    int bq = blockIdx.x;
    int t = threadIdx.x;
    if (t >= M_) return;
    const float* p = q + (size_t)bq * (C_ * M_) + t;
    float ss = 0.f;
#pragma unroll 8
    for (int c = 0; c < C_; c++) { float v = p[(size_t)c * M_]; ss = fmaf(v, v, ss); }
    g_qinv[bq * M_ + t] = 1.0f / (sqrtf(ss) + EPS_);
}

__global__ void snorm_k(const float* __restrict__ s) {
    int bj = blockIdx.x;
    int t = threadIdx.x;
    if (t >= M_) return;
    const float* p = s + (size_t)bj * (C_ * M_) + t;
    float ss = 0.f;
#pragma unroll 8
    for (int c = 0; c < C_; c++) { float v = p[(size_t)c * M_]; ss = fmaf(v, v, ss); }
    int b = bj / J_, j = bj % J_;
    g_sinv[b * COLS_ + j * M_ + t] = 1.0f / (sqrtf(ss) + EPS_);
}

// ---------------------------------------------------------------------------
// Main kernel: one CTA per (b,q). 100x2500 GEMM (K=640), k-paired f32x2 FMAs,
// cp.async double-buffered staging into k-transposed smem tiles, fused
// max/argmax epilogue, smem-resident running stats.
// ---------------------------------------------------------------------------
__global__ __launch_bounds__(256, 3) void dmn4_main_k(
    const float* __restrict__ sup,   // [B_, J_, C_, M_]
    const float* __restrict__ qry,   // [B_, Q_, C_, M_]
    float* __restrict__ pred)        // [BQ_, NW_]
{
    // k-transposed staging tiles: [row][k] with k-stride QSTR_ (even -> 8B align)
    __shared__ __align__(16) float smQt[2][M_ * QSTR_];   // 14400 B
    __shared__ __align__(16) float smSt[2][NT_ * QSTR_];  //  9216 B
    __shared__ float smSinv[NT_];
    __shared__ float smQiv[M_];
    __shared__ float smPV[M_][16];
    __shared__ unsigned short smPI[M_][16];
    __shared__ float smCmax[M_][NW_];
    __shared__ float smGv[M_];
    __shared__ int   smGi[M_];
    __shared__ int   smNear[M_];
    __shared__ float smDiff[M_];
    __shared__ float smMask[M_];

    const int bq = blockIdx.x;
    const int b  = bq / Q_;
    const int tid = threadIdx.x;
    const int tx = tid & 15;     // owns cols {tx, tx+16, tx+32, tx+48} of tile
    const int ty = tid >> 4;     // m rows ty + 16*i
    const int nm = (ty < 4) ? 7 : 6;

    const float* gq0 = qry + (size_t)bq * (C_ * M_);
    const float* gs0 = sup + (size_t)b * (J_ * C_ * M_);

    // smem u32 bases
    const unsigned aQ0 = (unsigned)__cvta_generic_to_shared(&smQt[0][0]);
    const unsigned aQ1 = (unsigned)__cvta_generic_to_shared(&smQt[1][0]);
    const unsigned aS0 = (unsigned)__cvta_generic_to_shared(&smSt[0][0]);
    const unsigned aS1 = (unsigned)__cvta_generic_to_shared(&smSt[1][0]);

    // init stats + qiv cache
    if (tid < M_) {
        smQiv[tid] = g_qinv[bq * M_ + tid];
        smGv[tid] = -FLT_MAX;
        smGi[tid] = 0;
#pragma unroll
        for (int w = 0; w < NW_; w++) smCmax[tid][w] = -FLT_MAX;
    }

    // per-thread q staging dsts: element e = tid + 256*j of chunk (layout kk*100+m)
    int qdst[7];
#pragma unroll
    for (int j = 0; j < 7; j++) {
        int e = tid + 256 * j;          // j==6 valid only tid<64
        int kk = e / M_, m = e - kk * M_;
        qdst[j] = (m * QSTR_ + kk) * 4; // byte offset
    }
    // per-thread s staging dsts: e = tid + 256*t, kk = e>>6, nl = e&63
    int sdst[4];
#pragma unroll
    for (int t = 0; t < 4; t++) {
        int e = tid + 256 * t;
        int kk = e >> 6, nl = e & 63;
        sdst[t] = (nl * QSTR_ + kk) * 4;
    }

    for (int nt = 0; nt < NTILES_; nt++) {
        const int col0 = nt * NT_;

        if (tid < NT_) {
            int col = col0 + tid;
            smSinv[tid] = (col < COLS_) ? g_sinv[b * COLS_ + col] : 0.f;
        }

        // per-tile s global offsets (chunk-invariant part) + validity
        int sgo[4], ssz[4];
#pragma unroll
        for (int t = 0; t < 4; t++) {
            int e = tid + 256 * t;
            int kk = e >> 6, nl = e & 63;
            int col = col0 + nl;
            int ok = (col < COLS_);
            int cc = ok ? col : 0;
            int j = cc / M_, ms = cc - j * M_;
            sgo[t] = (j * C_ + kk) * M_ + ms;
            ssz[t] = ok ? 4 : 0;
        }

        // acc[i][c]: f32x2, lanes = (even-k, odd-k) partials for col tx+16c
        ull acc[7][4];
#pragma unroll
        for (int i = 0; i < 7; i++)
#pragma unroll
            for (int c = 0; c < 4; c++) acc[i][c] = 0ull;

        // ---- preload chunk 0 into buffer 0 ----
        {
            const float* gq = gq0 + tid;
#pragma unroll
            for (int j = 0; j < 6; j++) cpa4u(aQ0 + qdst[j], gq + 256 * j);
            if (tid < 64) cpa4u(aQ0 + qdst[6], gq + 256 * 6);
#pragma unroll
            for (int t = 0; t < 4; t++) cpa4(aS0 + sdst[t], gs0 + sgo[t], ssz[t]);
            CP_COMMIT();
        }

        int buf = 0;
        for (int c = 0; c < NCH_; c++) {
            CP_WAIT0();
            __syncthreads();

            if (c < NCH_ - 1) {
                const int koff = (c + 1) * (KC_ * M_);
                const unsigned aQ = buf ? aQ0 : aQ1;
                const unsigned aS = buf ? aS0 : aS1;
                const float* gq = gq0 + koff + tid;
#pragma unroll
                for (int j = 0; j < 6; j++) cpa4u(aQ + qdst[j], gq + 256 * j);
                if (tid < 64) cpa4u(aQ + qdst[6], gq + 256 * 6);
#pragma unroll
                for (int t = 0; t < 4; t++)
                    cpa4(aS + sdst[t], gs0 + sgo[t] + koff, ssz[t]);
                CP_COMMIT();
            }

            // compute on current buffer: 8 kk-pairs
            {
                const float* qb = smQt[buf];
                const float* sb = smSt[buf];
#pragma unroll
                for (int kk2 = 0; kk2 < KC_ / 2; kk2++) {
                    ull sp0 = *(const ull*)&sb[(tx     ) * QSTR_ + 2 * kk2];
                    ull sp1 = *(const ull*)&sb[(tx + 16) * QSTR_ + 2 * kk2];
                    ull sp2 = *(const ull*)&sb[(tx + 32) * QSTR_ + 2 * kk2];
                    ull sp3 = *(const ull*)&sb[(tx + 48) * QSTR_ + 2 * kk2];
#pragma unroll
                    for (int i = 0; i < 7; i++) {
                        if (i < nm) {
                            ull qp = *(const ull*)&qb[(ty + 16 * i) * QSTR_ + 2 * kk2];
                            fma2(acc[i][0], qp, sp0);
                            fma2(acc[i][1], qp, sp1);
                            fma2(acc[i][2], qp, sp2);
                            fma2(acc[i][3], qp, sp3);
                        }
                    }
                }
            }
            buf ^= 1;
        }

        // ---- epilogue: per-thread max/argmax over its 4 (scattered) cols ----
#pragma unroll
        for (int i = 0; i < 7; i++) {
            if (i < nm) {
                int m = ty + 16 * i;
                float qiv = smQiv[m];
                float best = -FLT_MAX;
                int bidx = 0;
#pragma unroll
                for (int c = 0; c < 4; c++) {
                    int nl = tx + 16 * c;
                    int col = col0 + nl;
                    if (col < COLS_) {
                        float lo, hi;
                        unpack2(lo, hi, acc[i][c]);
                        float v = (lo + hi) * qiv * smSinv[nl];
                        if (v > best) { best = v; bidx = col; }
                    }
                }
                smPV[m][tx] = best;
                smPI[m][tx] = (unsigned short)bidx;
            }
        }
        __syncthreads();

        // ---- reducer: thread m folds 16 entries into smem-resident stats ----
        if (tid < M_) {
            float cm[NW_];
#pragma unroll
            for (int w = 0; w < NW_; w++) cm[w] = smCmax[tid][w];
            float gv = smGv[tid];
            int   gi = smGi[tid];
#pragma unroll
            for (int e = 0; e < 16; e++) {
                float v = smPV[tid][e];
                int idx = smPI[tid][e];
                int w = idx / MS_;
                if (v > cm[w]) cm[w] = v;
                if (v > gv || (v == gv && idx < gi)) { gv = v; gi = idx; }
            }
#pragma unroll
            for (int w = 0; w < NW_; w++) smCmax[tid][w] = cm[w];
            smGv[tid] = gv;
            smGi[tid] = gi;
        }
        __syncthreads();
    }

    // ---- top-2 over class maxes; publish per-m stats ----
    if (tid < M_) {
        float m1 = -FLT_MAX, m2 = -FLT_MAX;
#pragma unroll
        for (int w = 0; w < NW_; w++) {
            float v = smCmax[tid][w];
            if (v > m1) { m2 = m1; m1 = v; }
            else if (v > m2) { m2 = v; }
        }
        smDiff[tid] = m1 - m2;
        smNear[tid] = smGi[tid];
    }
    __syncthreads();

    // mutual-nearest: m kept iff m == argmax_{m'} (near[m']==slot ? diff[m'] : 0)
    if (tid < M_) {
        int slot = smNear[tid];
        float best = -1.0f;
        int idx = -1;
        for (int mp = 0; mp < M_; mp++) {
            float v = (smNear[mp] == slot) ? smDiff[mp] : 0.0f;
            if (v > best) { best = v; idx = mp; }
        }
        smMask[tid] = (idx == tid) ? TEMP_ : 0.0f;
    }
    __syncthreads();

    if (tid < NW_) {
        float p = 0.f;
        for (int m = 0; m < M_; m++)
            p += smCmax[m][tid] * smMask[m];
        pred[bq * NW_ + tid] = p;
    }
}

// ---------------------------------------------------------------------------
// Final loss: log-softmax NLL, deterministic tree reduction.
// ---------------------------------------------------------------------------
__global__ void loss_k(const float* __restrict__ pred,
                       const int* __restrict__ qy,
                       float* __restrict__ out)
{
    __shared__ float part[512];
    int t = threadIdx.x;
    float v = 0.f;
    if (t < BQ_) {
        const float* p = pred + t * NW_;
        float mx = p[0];
#pragma unroll
        for (int w = 1; w < NW_; w++) mx = fmaxf(mx, p[w]);
        float se = 0.f;
#pragma unroll
        for (int w = 0; w < NW_; w++) se += expf(p[w] - mx);
        float lse = mx + logf(se);
        int y = qy[t];
        v = p[y] - lse;
    }
    part[t] = v;
    __syncthreads();
    for (int s = 256; s > 0; s >>= 1) {
        if (t < s) part[t] += part[t + s];
        __syncthreads();
    }
    if (t == 0) out[0] = -part[0] / (float)BQ_;
}

// ---------------------------------------------------------------------------
extern "C" void kernel_launch(void* const* d_in, const int* in_sizes, int n_in,
                              void* d_out, int out_size)
{
    const float* support_xf = (const float*)d_in[0];   // [4,25,640,100]
    const float* query_xf   = (const float*)d_in[2];   // [4,75,640,100]
    const int*   query_y    = (const int*)d_in[3];     // [4,75]
    float* out = (float*)d_out;

    float* pred; cudaGetSymbolAddress((void**)&pred, g_pred);

    qnorm_k<<<BQ_, 128>>>(query_xf);
    snorm_k<<<B_ * J_, 128>>>(support_xf);
    dmn4_main_k<<<BQ_, 256>>>(support_xf, query_xf, pred);
    loss_k<<<1, 512>>>(pred, query_y, out);
}

// round 7
// speedup vs baseline: 2.7558x; 1.5165x over previous
#include <cuda_runtime.h>
#include <cuda_bf16.h>
#include <math.h>
#include <float.h>
#include <stdint.h>

typedef unsigned long long ull;

// Problem constants
#define B_      4
#define Q_      75
#define BQ_     300
#define C_      640
#define M_      100
#define J_      25
#define NW_     5
#define MS_     500
#define COLS_   2500
#define ROWSPB_ 7680          // padded rows per b (7500 -> 60*128)
#define CPAD_   2560          // padded cols (2500 -> 10*256)
#define RB_     60            // row blocks of 128
#define CB_     10            // col blocks of 256
#define SEG_    6
#define NCHUNK_ 60            // 6 segments * 10 k-chunks of 64
#define EPS_    1e-8f
#define TEMP_   2.0f

// Static device scratch (no allocation). bf16 component tensors, k-major.
__device__ __align__(128) __nv_bfloat16 g_A[(size_t)B_ * 3 * ROWSPB_ * C_]; // 118MB
__device__ __align__(128) __nv_bfloat16 g_B[(size_t)B_ * 3 * CPAD_ * C_];   // 39MB
__device__ float g_qinv[BQ_ * M_];
__device__ float g_sinv[B_ * COLS_];
__device__ float g_pcm[(size_t)B_ * ROWSPB_ * CB_ * NW_];
__device__ float g_pgv[(size_t)B_ * ROWSPB_ * CB_];
__device__ int   g_pgi[(size_t)B_ * ROWSPB_ * CB_];
__device__ float g_pred[BQ_ * NW_];

// segment -> component maps: a*b = hh + hm + mh + mm + hl + lh
__constant__ int c_mapA[SEG_] = {0, 0, 1, 1, 0, 2};
__constant__ int c_mapB[SEG_] = {0, 1, 0, 1, 2, 0};

__device__ __forceinline__ void cpa16(uint32_t dst, const void* src) {
    asm volatile("cp.async.cg.shared.global [%0], [%1], 16;" :: "r"(dst), "l"(src));
}
__device__ __forceinline__ void ldsm4(uint32_t* r, uint32_t addr) {
    asm volatile("ldmatrix.sync.aligned.m8n8.x4.shared.b16 {%0,%1,%2,%3}, [%4];"
        : "=r"(r[0]), "=r"(r[1]), "=r"(r[2]), "=r"(r[3]) : "r"(addr));
}
__device__ __forceinline__ void hmma(float* d, const uint32_t* a, uint32_t b0, uint32_t b1) {
    asm volatile("mma.sync.aligned.m16n8k16.row.col.f32.bf16.bf16.f32 "
        "{%0,%1,%2,%3}, {%4,%5,%6,%7}, {%8,%9}, {%0,%1,%2,%3};"
        : "+f"(d[0]), "+f"(d[1]), "+f"(d[2]), "+f"(d[3])
        : "r"(a[0]), "r"(a[1]), "r"(a[2]), "r"(a[3]), "r"(b0), "r"(b1));
}

// ---------------------------------------------------------------------------
// Inverse-norm kernels
// ---------------------------------------------------------------------------
__global__ void qnorm_k(const float* __restrict__ q) {
    int bq = blockIdx.x, t = threadIdx.x;
    if (t >= M_) return;
    const float* p = q + (size_t)bq * (C_ * M_) + t;
    float ss = 0.f;
#pragma unroll 8
    for (int c = 0; c < C_; c++) { float v = p[(size_t)c * M_]; ss = fmaf(v, v, ss); }
    g_qinv[bq * M_ + t] = 1.0f / (sqrtf(ss) + EPS_);
}
__global__ void snorm_k(const float* __restrict__ s) {
    int bj = blockIdx.x, t = threadIdx.x;
    if (t >= M_) return;
    const float* p = s + (size_t)bj * (C_ * M_) + t;
    float ss = 0.f;
#pragma unroll 8
    for (int c = 0; c < C_; c++) { float v = p[(size_t)c * M_]; ss = fmaf(v, v, ss); }
    int b = bj / J_, j = bj % J_;
    g_sinv[b * COLS_ + j * M_ + t] = 1.0f / (sqrtf(ss) + EPS_);
}

// ---------------------------------------------------------------------------
// Conversion: fp32 -> 3 bf16 components, k-major rows (transpose via smem).
// ---------------------------------------------------------------------------
__global__ __launch_bounds__(256) void convA_k(const float* __restrict__ qry) {
    const int cb64 = blockIdx.x;           // k-block of 64 channels
    const int bq = blockIdx.y;
    const int b = bq / Q_, q = bq - b * Q_;
    const int tid = threadIdx.x;
    __shared__ float sT[64][101];

    const float* src = qry + ((size_t)bq * C_ + cb64 * 64) * M_;
    for (int e = tid; e < 64 * M_; e += 256)
        sT[e / M_][e % M_] = src[e];               // coalesced (m contiguous)
    __syncthreads();

    const size_t compStride = (size_t)ROWSPB_ * C_;
    for (int e = tid; e < M_ * 64; e += 256) {
        int m = e >> 6, cc = e & 63;
        float v = sT[cc][m];
        __nv_bfloat16 h = __float2bfloat16(v);
        float r1 = v - __bfloat162float(h);
        __nv_bfloat16 md = __float2bfloat16(r1);
        __nv_bfloat16 lo = __float2bfloat16(r1 - __bfloat162float(md));
        size_t rg = (size_t)q * M_ + m;
        size_t off = ((size_t)b * 3 * ROWSPB_ + rg) * C_ + cb64 * 64 + cc;
        g_A[off] = h;
        g_A[off + compStride] = md;
        g_A[off + 2 * compStride] = lo;
    }
}

__global__ __launch_bounds__(256) void convB_k(const float* __restrict__ sup) {
    const int cb64 = blockIdx.x;
    const int bj = blockIdx.y;
    const int b = bj / J_, j = bj - b * J_;
    const int tid = threadIdx.x;
    __shared__ float sT[64][101];

    const float* src = sup + ((size_t)bj * C_ + cb64 * 64) * M_;
    for (int e = tid; e < 64 * M_; e += 256)
        sT[e / M_][e % M_] = src[e];
    __syncthreads();

    const size_t compStride = (size_t)CPAD_ * C_;
    for (int e = tid; e < M_ * 64; e += 256) {
        int m = e >> 6, cc = e & 63;
        float v = sT[cc][m];
        __nv_bfloat16 h = __float2bfloat16(v);
        float r1 = v - __bfloat162float(h);
        __nv_bfloat16 md = __float2bfloat16(r1);
        __nv_bfloat16 lo = __float2bfloat16(r1 - __bfloat162float(md));
        size_t rg = (size_t)j * M_ + m;
        size_t off = ((size_t)b * 3 * CPAD_ + rg) * C_ + cb64 * 64 + cc;
        g_B[off] = h;
        g_B[off + compStride] = md;
        g_B[off + 2 * compStride] = lo;
    }
}

// ---------------------------------------------------------------------------
// Main HMMA GEMM: CTA tile 128 rows x 256 cols, K_eff = 6*640 bf16.
// 8 warps (2m x 4n), warp tile 64x64 via m16n8k16. Fused reduction epilogue.
// ---------------------------------------------------------------------------
extern __shared__ char dynsm[];

__global__ __launch_bounds__(256, 1) void mma_gemm_k() {
    const int rb = blockIdx.x, cb = blockIdx.y, b = blockIdx.z;
    const int tid = threadIdx.x, lane = tid & 31, wid = tid >> 5;
    const int wm = wid >> 2, wn = wid & 3;
    const int l15 = lane & 15, hi = lane >> 4;

    __shared__ float sSinv[256];

    uintptr_t basep = ((uintptr_t)dynsm + 1023) & ~(uintptr_t)1023;
    const uint32_t aBuf = (uint32_t)__cvta_generic_to_shared((void*)basep);
    // layout per buffer: A (16KB) + B (32KB); two buffers
    const uint32_t aA[2] = {aBuf, aBuf + 49152u};
    const uint32_t aB[2] = {aBuf + 16384u, aBuf + 49152u + 16384u};
    float* smSD = (float*)basep;   // epilogue D tile, stride 132 floats

    { int colg = cb * 256 + tid;
      sSinv[tid] = (colg < COLS_) ? g_sinv[b * COLS_ + colg] : 0.f; }

    // swizzled k-byte offsets per k16-step (same for A and B: rows are 128B)
    uint32_t kbs[4];
#pragma unroll
    for (int k = 0; k < 4; k++)
        kbs[k] = (uint32_t)((k * 32 + hi * 16) ^ ((lane & 7) * 16));
    uint32_t rowA[4], rowB[4];
#pragma unroll
    for (int mf = 0; mf < 4; mf++) rowA[mf] = (uint32_t)(wm * 64 + mf * 16 + l15) * 128u;
#pragma unroll
    for (int nfp = 0; nfp < 4; nfp++) rowB[nfp] = (uint32_t)(wn * 64 + nfp * 16 + l15) * 128u;

    float d[4][8][4];
#pragma unroll
    for (int mf = 0; mf < 4; mf++)
#pragma unroll
        for (int nf = 0; nf < 8; nf++)
#pragma unroll
            for (int r = 0; r < 4; r++) d[mf][nf][r] = 0.f;

    const char* gA = (const char*)g_A;
    const char* gB = (const char*)g_B;

    auto issue = [&](int c) {
        int seg = c / 10, cc = c - seg * 10;
        int p = c & 1;
        size_t baA = ((size_t)(b * 3 + c_mapA[seg]) * ROWSPB_ + rb * 128) * (C_ * 2)
                     + (size_t)cc * 128;
        size_t baB = ((size_t)(b * 3 + c_mapB[seg]) * CPAD_ + cb * 256) * (C_ * 2)
                     + (size_t)cc * 128;
#pragma unroll
        for (int i = 0; i < 4; i++) {      // A: 128 rows x 8 granules
            int g = tid + 256 * i;
            int r = g >> 3; uint32_t c16 = (uint32_t)(g & 7) * 16;
            cpa16(aA[p] + (uint32_t)r * 128 + (c16 ^ ((uint32_t)(r & 7) * 16)),
                  gA + baA + (size_t)r * (C_ * 2) + c16);
        }
#pragma unroll
        for (int i = 0; i < 8; i++) {      // B: 256 rows x 8 granules
            int g = tid + 256 * i;
            int r = g >> 3; uint32_t c16 = (uint32_t)(g & 7) * 16;
            cpa16(aB[p] + (uint32_t)r * 128 + (c16 ^ ((uint32_t)(r & 7) * 16)),
                  gB + baB + (size_t)r * (C_ * 2) + c16);
        }
        asm volatile("cp.async.commit_group;");
    };

    issue(0);
    for (int c = 0; c < NCHUNK_; c++) {
        if (c < NCHUNK_ - 1) {
            issue(c + 1);
            asm volatile("cp.async.wait_group 1;");
        } else {
            asm volatile("cp.async.wait_group 0;");
        }
        __syncthreads();
        const int p = c & 1;
#pragma unroll
        for (int ks = 0; ks < 4; ks++) {
            uint32_t afr[4][4], bfr[4][4];
#pragma unroll
            for (int mf = 0; mf < 4; mf++) ldsm4(afr[mf], aA[p] + rowA[mf] + kbs[ks]);
#pragma unroll
            for (int nfp = 0; nfp < 4; nfp++) ldsm4(bfr[nfp], aB[p] + rowB[nfp] + kbs[ks]);
#pragma unroll
            for (int mf = 0; mf < 4; mf++)
#pragma unroll
                for (int nf = 0; nf < 8; nf++)
                    hmma(d[mf][nf], afr[mf],
                         bfr[nf >> 1][nf & 1], bfr[nf >> 1][(nf & 1) + 2]);
        }
        __syncthreads();
    }

    // ---- epilogue: two 128x128 halves through smem, fused reductions ----
    float cmax[NW_];
#pragma unroll
    for (int w = 0; w < NW_; w++) cmax[w] = -FLT_MAX;
    float gv = -FLT_MAX;
    int gi = 0;

    const int rg = rb * 128 + tid;                 // reducer row (tid<128)
    const bool rvalid = (tid < 128) && (rg < Q_ * M_);
    float qiv = 0.f;
    if (rvalid) {
        int q = rg / M_, m = rg - q * M_;
        qiv = g_qinv[(b * Q_ + q) * M_ + m];
    }

#pragma unroll
    for (int h = 0; h < 2; h++) {
        __syncthreads();
        if ((wn >> 1) == h) {
#pragma unroll
            for (int mf = 0; mf < 4; mf++)
#pragma unroll
                for (int nf = 0; nf < 8; nf++) {
                    int row = wm * 64 + mf * 16 + (lane >> 2);
                    int coll = (wn & 1) * 64 + nf * 8 + (lane & 3) * 2;
                    smSD[row * 132 + coll]       = d[mf][nf][0];
                    smSD[row * 132 + coll + 1]   = d[mf][nf][1];
                    smSD[(row + 8) * 132 + coll]     = d[mf][nf][2];
                    smSD[(row + 8) * 132 + coll + 1] = d[mf][nf][3];
                }
        }
        __syncthreads();
        if (rvalid) {
            for (int cl = 0; cl < 128; cl++) {
                int colg = cb * 256 + h * 128 + cl;
                if (colg < COLS_) {
                    float v = smSD[tid * 132 + cl] * qiv * sSinv[h * 128 + cl];
                    int cls = colg / MS_;
                    if (v > cmax[cls]) cmax[cls] = v;
                    if (v > gv) { gv = v; gi = colg; }   // ascending -> first-index ties
                }
            }
        }
    }

    if (rvalid) {
        size_t pr = ((size_t)b * ROWSPB_ + rg) * CB_ + cb;
#pragma unroll
        for (int w = 0; w < NW_; w++) g_pcm[pr * NW_ + w] = cmax[w];
        g_pgv[pr] = gv;
        g_pgi[pr] = gi;
    }
}

// ---------------------------------------------------------------------------
// Merge partials + mutual-nearest mask + predict (one block per (b,q)).
// ---------------------------------------------------------------------------
__global__ __launch_bounds__(128) void mask_k() {
    const int bq = blockIdx.x;
    const int b = bq / Q_;
    const int tid = threadIdx.x;

    __shared__ float sCm[M_][NW_];
    __shared__ float sDiff[M_];
    __shared__ int   sNear[M_];
    __shared__ float sMask[M_];

    if (tid < M_) {
        int rg = (bq % Q_) * M_ + tid;
        size_t basep = ((size_t)b * ROWSPB_ + rg) * CB_;
        float cm[NW_];
#pragma unroll
        for (int w = 0; w < NW_; w++) cm[w] = -FLT_MAX;
        float gv = -FLT_MAX;
        int gi = 0;
        for (int t = 0; t < CB_; t++) {          // ascending col-block order
            size_t p = basep + t;
#pragma unroll
            for (int w = 0; w < NW_; w++) {
                float v = g_pcm[p * NW_ + w];
                if (v > cm[w]) cm[w] = v;
            }
            float v = g_pgv[p];
            if (v > gv) { gv = v; gi = g_pgi[p]; }
        }
        float m1 = -FLT_MAX, m2 = -FLT_MAX;
#pragma unroll
        for (int w = 0; w < NW_; w++) {
            float v = cm[w];
            if (v > m1) { m2 = m1; m1 = v; }
            else if (v > m2) { m2 = v; }
            sCm[tid][w] = v;
        }
        sDiff[tid] = m1 - m2;
        sNear[tid] = gi;
    }
    __syncthreads();

    if (tid < M_) {
        int slot = sNear[tid];
        float best = -1.0f;
        int idx = -1;
        for (int mp = 0; mp < M_; mp++) {
            float v = (sNear[mp] == slot) ? sDiff[mp] : 0.0f;
            if (v > best) { best = v; idx = mp; }
        }
        sMask[tid] = (idx == tid) ? TEMP_ : 0.0f;
    }
    __syncthreads();

    if (tid < NW_) {
        float p = 0.f;
        for (int m = 0; m < M_; m++)
            p += sCm[m][tid] * sMask[m];
        g_pred[bq * NW_ + tid] = p;
    }
}

// ---------------------------------------------------------------------------
// Loss: log-softmax NLL, deterministic tree reduction.
// ---------------------------------------------------------------------------
__global__ void loss_k(const int* __restrict__ qy, float* __restrict__ out) {
    __shared__ float part[512];
    int t = threadIdx.x;
    float v = 0.f;
    if (t < BQ_) {
        const float* p = g_pred + t * NW_;
        float mx = p[0];
#pragma unroll
        for (int w = 1; w < NW_; w++) mx = fmaxf(mx, p[w]);
        float se = 0.f;
#pragma unroll
        for (int w = 0; w < NW_; w++) se += expf(p[w] - mx);
        float lse = mx + logf(se);
        int y = qy[t];
        v = p[y] - lse;
    }
    part[t] = v;
    __syncthreads();
    for (int s = 256; s > 0; s >>= 1) {
        if (t < s) part[t] += part[t + s];
        __syncthreads();
    }
    if (t == 0) out[0] = -part[0] / (float)BQ_;
}

// ---------------------------------------------------------------------------
extern "C" void kernel_launch(void* const* d_in, const int* in_sizes, int n_in,
                              void* d_out, int out_size)
{
    const float* support_xf = (const float*)d_in[0];   // [4,25,640,100]
    const float* query_xf   = (const float*)d_in[2];   // [4,75,640,100]
    const int*   query_y    = (const int*)d_in[3];     // [4,75]
    float* out = (float*)d_out;

    // Idempotent; first (pre-capture) call makes it stick.
    cudaFuncSetAttribute(mma_gemm_k, cudaFuncAttributeMaxDynamicSharedMemorySize, 99328);

    qnorm_k<<<BQ_, 128>>>(query_xf);
    snorm_k<<<B_ * J_, 128>>>(support_xf);
    convA_k<<<dim3(10, BQ_), 256>>>(query_xf);
    convB_k<<<dim3(10, B_ * J_), 256>>>(support_xf);
    mma_gemm_k<<<dim3(RB_, CB_, B_), 256, 99328>>>();
    mask_k<<<BQ_, 128>>>();
    loss_k<<<1, 512>>>(query_y, out);
}

// round 9
// speedup vs baseline: 2.7912x; 1.0128x over previous
#include <cuda_runtime.h>
#include <cuda_bf16.h>
#include <math.h>
#include <float.h>
#include <stdint.h>

typedef unsigned long long ull;

// Problem constants
#define B_      4
#define Q_      75
#define BQ_     300
#define C_      640
#define M_      100
#define J_      25
#define NW_     5
#define MS_     500
#define COLS_   2500
#define ROWSPB_ 7680          // padded rows per b (7500 -> 60*128)
#define CPAD_   2560          // padded cols (2500 -> 10*256)
#define RB_     60            // row blocks of 128
#define CB_     10            // col blocks of 256
#define SEG_    6
#define NCHUNK_ 60            // 6 segments * 10 k-chunks of 64
#define NSTAGE_ 4
#define EPS_    1e-8f
#define TEMP_   2.0f

// Static device scratch (no allocation). bf16 component tensors, k-major.
__device__ __align__(128) __nv_bfloat16 g_A[(size_t)B_ * 3 * ROWSPB_ * C_]; // 118MB
__device__ __align__(128) __nv_bfloat16 g_B[(size_t)B_ * 3 * CPAD_ * C_];   // 39MB
__device__ float g_qinv[BQ_ * M_];
__device__ float g_sinv[B_ * COLS_];
__device__ float g_pcm[(size_t)B_ * ROWSPB_ * CB_ * NW_];
__device__ float g_pgv[(size_t)B_ * ROWSPB_ * CB_];
__device__ int   g_pgi[(size_t)B_ * ROWSPB_ * CB_];
__device__ float g_pred[BQ_ * NW_];

// segment -> component maps: a*b = hh + hm + mh + mm + hl + lh
__constant__ int c_mapA[SEG_] = {0, 0, 1, 1, 0, 2};
__constant__ int c_mapB[SEG_] = {0, 1, 0, 1, 2, 0};

__device__ __forceinline__ void cpa16(uint32_t dst, const void* src) {
    asm volatile("cp.async.cg.shared.global [%0], [%1], 16;" :: "r"(dst), "l"(src));
}
__device__ __forceinline__ void ldsm4(uint32_t* r, uint32_t addr) {
    asm volatile("ldmatrix.sync.aligned.m8n8.x4.shared.b16 {%0,%1,%2,%3}, [%4];"
        : "=r"(r[0]), "=r"(r[1]), "=r"(r[2]), "=r"(r[3]) : "r"(addr));
}
__device__ __forceinline__ void hmma(float* d, const uint32_t* a, uint32_t b0, uint32_t b1) {
    asm volatile("mma.sync.aligned.m16n8k16.row.col.f32.bf16.bf16.f32 "
        "{%0,%1,%2,%3}, {%4,%5,%6,%7}, {%8,%9}, {%0,%1,%2,%3};"
        : "+f"(d[0]), "+f"(d[1]), "+f"(d[2]), "+f"(d[3])
        : "r"(a[0]), "r"(a[1]), "r"(a[2]), "r"(a[3]), "r"(b0), "r"(b1));
}

// ---------------------------------------------------------------------------
// Inverse-norm kernels
// ---------------------------------------------------------------------------
__global__ void qnorm_k(const float* __restrict__ q) {
    int bq = blockIdx.x, t = threadIdx.x;
    if (t >= M_) return;
    const float* p = q + (size_t)bq * (C_ * M_) + t;
    float ss = 0.f;
#pragma unroll 8
    for (int c = 0; c < C_; c++) { float v = p[(size_t)c * M_]; ss = fmaf(v, v, ss); }
    g_qinv[bq * M_ + t] = 1.0f / (sqrtf(ss) + EPS_);
}
__global__ void snorm_k(const float* __restrict__ s) {
    int bj = blockIdx.x, t = threadIdx.x;
    if (t >= M_) return;
    const float* p = s + (size_t)bj * (C_ * M_) + t;
    float ss = 0.f;
#pragma unroll 8
    for (int c = 0; c < C_; c++) { float v = p[(size_t)c * M_]; ss = fmaf(v, v, ss); }
    int b = bj / J_, j = bj % J_;
    g_sinv[b * COLS_ + j * M_ + t] = 1.0f / (sqrtf(ss) + EPS_);
}

// ---------------------------------------------------------------------------
// Conversion: fp32 -> 3 bf16 components, k-major rows (transpose via smem).
// ---------------------------------------------------------------------------
__global__ __launch_bounds__(256) void convA_k(const float* __restrict__ qry) {
    const int cb64 = blockIdx.x;           // k-block of 64 channels
    const int bq = blockIdx.y;
    const int b = bq / Q_, q = bq - b * Q_;
    const int tid = threadIdx.x;
    __shared__ float sT[64][101];

    const float* src = qry + ((size_t)bq * C_ + cb64 * 64) * M_;
    for (int e = tid; e < 64 * M_; e += 256)
        sT[e / M_][e % M_] = src[e];               // coalesced (m contiguous)
    __syncthreads();

    const size_t compStride = (size_t)ROWSPB_ * C_;
    for (int e = tid; e < M_ * 64; e += 256) {
        int m = e >> 6, cc = e & 63;
        float v = sT[cc][m];
        __nv_bfloat16 h = __float2bfloat16(v);
        float r1 = v - __bfloat162float(h);
        __nv_bfloat16 md = __float2bfloat16(r1);
        __nv_bfloat16 lo = __float2bfloat16(r1 - __bfloat162float(md));
        size_t rg = (size_t)q * M_ + m;
        size_t off = ((size_t)b * 3 * ROWSPB_ + rg) * C_ + cb64 * 64 + cc;
        g_A[off] = h;
        g_A[off + compStride] = md;
        g_A[off + 2 * compStride] = lo;
    }
}

__global__ __launch_bounds__(256) void convB_k(const float* __restrict__ sup) {
    const int cb64 = blockIdx.x;
    const int bj = blockIdx.y;
    const int b = bj / J_, j = bj - b * J_;
    const int tid = threadIdx.x;
    __shared__ float sT[64][101];

    const float* src = sup + ((size_t)bj * C_ + cb64 * 64) * M_;
    for (int e = tid; e < 64 * M_; e += 256)
        sT[e / M_][e % M_] = src[e];
    __syncthreads();

    const size_t compStride = (size_t)CPAD_ * C_;
    for (int e = tid; e < M_ * 64; e += 256) {
        int m = e >> 6, cc = e & 63;
        float v = sT[cc][m];
        __nv_bfloat16 h = __float2bfloat16(v);
        float r1 = v - __bfloat162float(h);
        __nv_bfloat16 md = __float2bfloat16(r1);
        __nv_bfloat16 lo = __float2bfloat16(r1 - __bfloat162float(md));
        size_t rg = (size_t)j * M_ + m;
        size_t off = ((size_t)b * 3 * CPAD_ + rg) * C_ + cb64 * 64 + cc;
        g_B[off] = h;
        g_B[off + compStride] = md;
        g_B[off + 2 * compStride] = lo;
    }
}

// ---------------------------------------------------------------------------
// Main HMMA GEMM: CTA tile 128 rows x 256 cols, K_eff = 6*640 bf16.
// 8 warps (2m x 4n), warp tile 64x64 via m16n8k16. 4-stage cp.async pipeline.
// Grid: x in [0,600) swizzled as 15rb x 10cb groups for L2 reuse; z = b.
// ---------------------------------------------------------------------------
extern __shared__ char dynsm[];

__global__ __launch_bounds__(256, 1) void mma_gemm_k() {
    const int gx = blockIdx.x, b = blockIdx.z;
    const int grp = gx / 150, t150 = gx - grp * 150;
    const int cb = t150 % 10, rb = grp * 15 + t150 / 10;

    const int tid = threadIdx.x, lane = tid & 31, wid = tid >> 5;
    const int wm = wid >> 2, wn = wid & 3;
    const int l15 = lane & 15, hi = lane >> 4;

    __shared__ float sSinv[256];

    uintptr_t basep = ((uintptr_t)dynsm + 1023) & ~(uintptr_t)1023;
    const uint32_t aBuf = (uint32_t)__cvta_generic_to_shared((void*)basep);
    // per stage: A (16KB) + B (32KB)
    uint32_t aA[NSTAGE_], aB[NSTAGE_];
#pragma unroll
    for (int s = 0; s < NSTAGE_; s++) {
        aA[s] = aBuf + (uint32_t)s * 49152u;
        aB[s] = aA[s] + 16384u;
    }
    float* smSD = (float*)basep;   // epilogue D tile, stride 132 floats

    { int colg = cb * 256 + tid;
      sSinv[tid] = (colg < COLS_) ? g_sinv[b * COLS_ + colg] : 0.f; }

    // swizzled k-byte offsets per k16-step (rows are 128B)
    uint32_t kbs[4];
#pragma unroll
    for (int k = 0; k < 4; k++)
        kbs[k] = (uint32_t)((k * 32 + hi * 16) ^ ((lane & 7) * 16));
    uint32_t rowA[4], rowB[4];
#pragma unroll
    for (int mf = 0; mf < 4; mf++) rowA[mf] = (uint32_t)(wm * 64 + mf * 16 + l15) * 128u;
#pragma unroll
    for (int nfp = 0; nfp < 4; nfp++) rowB[nfp] = (uint32_t)(wn * 64 + nfp * 16 + l15) * 128u;

    float d[4][8][4];
#pragma unroll
    for (int mf = 0; mf < 4; mf++)
#pragma unroll
        for (int nf = 0; nf < 8; nf++)
#pragma unroll
            for (int r = 0; r < 4; r++) d[mf][nf][r] = 0.f;

    const char* gA = (const char*)g_A;
    const char* gB = (const char*)g_B;

    auto issue = [&](int c) {
        int seg = c / 10, cc = c - seg * 10;
        int p = c & (NSTAGE_ - 1);
        size_t baA = ((size_t)(b * 3 + c_mapA[seg]) * ROWSPB_ + rb * 128) * (C_ * 2)
                     + (size_t)cc * 128;
        size_t baB = ((size_t)(b * 3 + c_mapB[seg]) * CPAD_ + cb * 256) * (C_ * 2)
                     + (size_t)cc * 128;
#pragma unroll
        for (int i = 0; i < 4; i++) {      // A: 128 rows x 8 granules
            int g = tid + 256 * i;
            int r = g >> 3; uint32_t c16 = (uint32_t)(g & 7) * 16;
            cpa16(aA[p] + (uint32_t)r * 128 + (c16 ^ ((uint32_t)(r & 7) * 16)),
                  gA + baA + (size_t)r * (C_ * 2) + c16);
        }
#pragma unroll
        for (int i = 0; i < 8; i++) {      // B: 256 rows x 8 granules
            int g = tid + 256 * i;
            int r = g >> 3; uint32_t c16 = (uint32_t)(g & 7) * 16;
            cpa16(aB[p] + (uint32_t)r * 128 + (c16 ^ ((uint32_t)(r & 7) * 16)),
                  gB + baB + (size_t)r * (C_ * 2) + c16);
        }
        asm volatile("cp.async.commit_group;");
    };

    // prologue: 3 chunks in flight
    issue(0); issue(1); issue(2);

    for (int c = 0; c < NCHUNK_; c++) {
        // wait until chunk c is complete (this thread's groups), then barrier
        if (c <= NCHUNK_ - 3)      asm volatile("cp.async.wait_group 2;");
        else if (c == NCHUNK_ - 2) asm volatile("cp.async.wait_group 1;");
        else                       asm volatile("cp.async.wait_group 0;");
        __syncthreads();

        // refill stage (c+3): its previous contents were consumed at c-1
        if (c + 3 < NCHUNK_) issue(c + 3);

        const int p = c & (NSTAGE_ - 1);
#pragma unroll
        for (int ks = 0; ks < 4; ks++) {
            uint32_t afr[4][4], bfr[4][4];
#pragma unroll
            for (int mf = 0; mf < 4; mf++) ldsm4(afr[mf], aA[p] + rowA[mf] + kbs[ks]);
#pragma unroll
            for (int nfp = 0; nfp < 4; nfp++) ldsm4(bfr[nfp], aB[p] + rowB[nfp] + kbs[ks]);
#pragma unroll
            for (int mf = 0; mf < 4; mf++)
#pragma unroll
                for (int nf = 0; nf < 8; nf++)
                    hmma(d[mf][nf], afr[mf],
                         bfr[nf >> 1][nf & 1], bfr[nf >> 1][(nf & 1) + 2]);
        }
    }
    __syncthreads();   // all warps done with last stage before smem reuse

    // ---- epilogue: two 128x128 halves through smem, fused reductions ----
    float cmax[NW_];
#pragma unroll
    for (int w = 0; w < NW_; w++) cmax[w] = -FLT_MAX;
    float gv = -FLT_MAX;
    int gi = 0;

    const int rg = rb * 128 + tid;                 // reducer row (tid<128)
    const bool rvalid = (tid < 128) && (rg < Q_ * M_);
    float qiv = 0.f;
    if (rvalid) {
        int q = rg / M_, m = rg - q * M_;
        qiv = g_qinv[(b * Q_ + q) * M_ + m];
    }

#pragma unroll
    for (int h = 0; h < 2; h++) {
        __syncthreads();
        if ((wn >> 1) == h) {
#pragma unroll
            for (int mf = 0; mf < 4; mf++)
#pragma unroll
                for (int nf = 0; nf < 8; nf++) {
                    int row = wm * 64 + mf * 16 + (lane >> 2);
                    int coll = (wn & 1) * 64 + nf * 8 + (lane & 3) * 2;
                    smSD[row * 132 + coll]       = d[mf][nf][0];
                    smSD[row * 132 + coll + 1]   = d[mf][nf][1];
                    smSD[(row + 8) * 132 + coll]     = d[mf][nf][2];
                    smSD[(row + 8) * 132 + coll + 1] = d[mf][nf][3];
                }
        }
        __syncthreads();
        if (rvalid) {
            for (int cl = 0; cl < 128; cl++) {
                int colg = cb * 256 + h * 128 + cl;
                if (colg < COLS_) {
                    float v = smSD[tid * 132 + cl] * qiv * sSinv[h * 128 + cl];
                    int cls = colg / MS_;
                    if (v > cmax[cls]) cmax[cls] = v;
                    if (v > gv) { gv = v; gi = colg; }   // ascending -> first-index ties
                }
            }
        }
    }

    if (rvalid) {
        size_t pr = ((size_t)b * ROWSPB_ + rg) * CB_ + cb;
#pragma unroll
        for (int w = 0; w < NW_; w++) g_pcm[pr * NW_ + w] = cmax[w];
        g_pgv[pr] = gv;
        g_pgi[pr] = gi;
    }
}

// ---------------------------------------------------------------------------
// Merge partials + mutual-nearest mask + predict (one block per (b,q)).
// ---------------------------------------------------------------------------
__global__ __launch_bounds__(128) void mask_k() {
    const int bq = blockIdx.x;
    const int b = bq / Q_;
    const int tid = threadIdx.x;

    __shared__ float sCm[M_][NW_];
    __shared__ float sDiff[M_];
    __shared__ int   sNear[M_];
    __shared__ float sMask[M_];

    if (tid < M_) {
        int rg = (bq % Q_) * M_ + tid;
        size_t basep = ((size_t)b * ROWSPB_ + rg) * CB_;
        float cm[NW_];
#pragma unroll
        for (int w = 0; w < NW_; w++) cm[w] = -FLT_MAX;
        float gv = -FLT_MAX;
        int gi = 0;
        for (int t = 0; t < CB_; t++) {          // ascending col-block order
            size_t p = basep + t;
#pragma unroll
            for (int w = 0; w < NW_; w++) {
                float v = g_pcm[p * NW_ + w];
                if (v > cm[w]) cm[w] = v;
            }
            float v = g_pgv[p];
            if (v > gv) { gv = v; gi = g_pgi[p]; }
        }
        float m1 = -FLT_MAX, m2 = -FLT_MAX;
#pragma unroll
        for (int w = 0; w < NW_; w++) {
            float v = cm[w];
            if (v > m1) { m2 = m1; m1 = v; }
            else if (v > m2) { m2 = v; }
            sCm[tid][w] = v;
        }
        sDiff[tid] = m1 - m2;
        sNear[tid] = gi;
    }
    __syncthreads();

    if (tid < M_) {
        int slot = sNear[tid];
        float best = -1.0f;
        int idx = -1;
        for (int mp = 0; mp < M_; mp++) {
            float v = (sNear[mp] == slot) ? sDiff[mp] : 0.0f;
            if (v > best) { best = v; idx = mp; }
        }
        sMask[tid] = (idx == tid) ? TEMP_ : 0.0f;
    }
    __syncthreads();

    if (tid < NW_) {
        float p = 0.f;
        for (int m = 0; m < M_; m++)
            p += sCm[m][tid] * sMask[m];
        g_pred[bq * NW_ + tid] = p;
    }
}

// ---------------------------------------------------------------------------
// Loss: log-softmax NLL, deterministic tree reduction.
// ---------------------------------------------------------------------------
__global__ void loss_k(const int* __restrict__ qy, float* __restrict__ out) {
    __shared__ float part[512];
    int t = threadIdx.x;
    float v = 0.f;
    if (t < BQ_) {
        const float* p = g_pred + t * NW_;
        float mx = p[0];
#pragma unroll
        for (int w = 1; w < NW_; w++) mx = fmaxf(mx, p[w]);
        float se = 0.f;
#pragma unroll
        for (int w = 0; w < NW_; w++) se += expf(p[w] - mx);
        float lse = mx + logf(se);
        int y = qy[t];
        v = p[y] - lse;
    }
    part[t] = v;
    __syncthreads();
    for (int s = 256; s > 0; s >>= 1) {
        if (t < s) part[t] += part[t + s];
        __syncthreads();
    }
    if (t == 0) out[0] = -part[0] / (float)BQ_;
}

// ---------------------------------------------------------------------------
extern "C" void kernel_launch(void* const* d_in, const int* in_sizes, int n_in,
                              void* d_out, int out_size)
{
    const float* support_xf = (const float*)d_in[0];   // [4,25,640,100]
    const float* query_xf   = (const float*)d_in[2];   // [4,75,640,100]
    const int*   query_y    = (const int*)d_in[3];     // [4,75]
    float* out = (float*)d_out;

    // Idempotent; first (pre-capture) call makes it stick.
    cudaFuncSetAttribute(mma_gemm_k, cudaFuncAttributeMaxDynamicSharedMemorySize,
                         NSTAGE_ * 49152);

    qnorm_k<<<BQ_, 128>>>(query_xf);
    snorm_k<<<B_ * J_, 128>>>(support_xf);
    convA_k<<<dim3(10, BQ_), 256>>>(query_xf);
    convB_k<<<dim3(10, B_ * J_), 256>>>(support_xf);
    mma_gemm_k<<<dim3(600, 1, B_), 256, NSTAGE_ * 49152>>>();
    mask_k<<<BQ_, 128>>>();
    loss_k<<<1, 512>>>(query_y, out);
}

// round 10
// speedup vs baseline: 4.7245x; 1.6926x over previous
#include <cuda_runtime.h>
#include <cuda_fp16.h>
#include <math.h>
#include <float.h>
#include <stdint.h>

typedef unsigned long long ull;

// Problem constants
#define B_      4
#define Q_      75
#define BQ_     300
#define C_      640
#define M_      100
#define J_      25
#define NW_     5
#define MS_     500
#define COLS_   2500
#define ROWSPB_ 7680          // padded rows per b (7500 -> 60*128)
#define CPAD_   2560          // padded cols (2500 -> 10*256)
#define RB_     60            // row blocks of 128
#define CB_     10            // col blocks of 256
#define SEG_    3             // fp16 split: hh, hm, mh
#define NCHUNK_ 30            // 3 segments * 10 k-chunks of 64
#define NSTAGE_ 4
#define EPS_    1e-8f
#define TEMP_   2.0f

// Static device scratch (no allocation). fp16 component tensors (h, m), k-major.
__device__ __align__(128) __half g_A[(size_t)B_ * 2 * ROWSPB_ * C_]; // 78.6MB
__device__ __align__(128) __half g_B[(size_t)B_ * 2 * CPAD_ * C_];   // 26.2MB
__device__ float g_qinv[BQ_ * M_];
__device__ float g_sinv[B_ * COLS_];
__device__ float g_pcm[(size_t)B_ * ROWSPB_ * CB_ * NW_];
__device__ float g_pgv[(size_t)B_ * ROWSPB_ * CB_];
__device__ int   g_pgi[(size_t)B_ * ROWSPB_ * CB_];
__device__ float g_pred[BQ_ * NW_];

// segment -> component maps: a*b ~= hh + hm + mh  (mm ~ 2^-24, negligible)
__constant__ int c_mapA[SEG_] = {0, 0, 1};
__constant__ int c_mapB[SEG_] = {0, 1, 0};

__device__ __forceinline__ void cpa16(uint32_t dst, const void* src) {
    asm volatile("cp.async.cg.shared.global [%0], [%1], 16;" :: "r"(dst), "l"(src));
}
__device__ __forceinline__ void ldsm4(uint32_t* r, uint32_t addr) {
    asm volatile("ldmatrix.sync.aligned.m8n8.x4.shared.b16 {%0,%1,%2,%3}, [%4];"
        : "=r"(r[0]), "=r"(r[1]), "=r"(r[2]), "=r"(r[3]) : "r"(addr));
}
__device__ __forceinline__ void hmma(float* d, const uint32_t* a, uint32_t b0, uint32_t b1) {
    asm volatile("mma.sync.aligned.m16n8k16.row.col.f32.f16.f16.f32 "
        "{%0,%1,%2,%3}, {%4,%5,%6,%7}, {%8,%9}, {%0,%1,%2,%3};"
        : "+f"(d[0]), "+f"(d[1]), "+f"(d[2]), "+f"(d[3])
        : "r"(a[0]), "r"(a[1]), "r"(a[2]), "r"(a[3]), "r"(b0), "r"(b1));
}

// ---------------------------------------------------------------------------
// Inverse-norm kernels
// ---------------------------------------------------------------------------
__global__ void qnorm_k(const float* __restrict__ q) {
    int bq = blockIdx.x, t = threadIdx.x;
    if (t >= M_) return;
    const float* p = q + (size_t)bq * (C_ * M_) + t;
    float ss = 0.f;
#pragma unroll 8
    for (int c = 0; c < C_; c++) { float v = p[(size_t)c * M_]; ss = fmaf(v, v, ss); }
    g_qinv[bq * M_ + t] = 1.0f / (sqrtf(ss) + EPS_);
}
__global__ void snorm_k(const float* __restrict__ s) {
    int bj = blockIdx.x, t = threadIdx.x;
    if (t >= M_) return;
    const float* p = s + (size_t)bj * (C_ * M_) + t;
    float ss = 0.f;
#pragma unroll 8
    for (int c = 0; c < C_; c++) { float v = p[(size_t)c * M_]; ss = fmaf(v, v, ss); }
    int b = bj / J_, j = bj % J_;
    g_sinv[b * COLS_ + j * M_ + t] = 1.0f / (sqrtf(ss) + EPS_);
}

// ---------------------------------------------------------------------------
// Conversion: fp32 -> 2 fp16 components (h, m), k-major rows (smem transpose).
// ---------------------------------------------------------------------------
__global__ __launch_bounds__(256) void convA_k(const float* __restrict__ qry) {
    const int cb64 = blockIdx.x;           // k-block of 64 channels
    const int bq = blockIdx.y;
    const int b = bq / Q_, q = bq - b * Q_;
    const int tid = threadIdx.x;
    __shared__ float sT[64][101];

    const float* src = qry + ((size_t)bq * C_ + cb64 * 64) * M_;
    for (int e = tid; e < 64 * M_; e += 256)
        sT[e / M_][e % M_] = src[e];               // coalesced (m contiguous)
    __syncthreads();

    const size_t compStride = (size_t)ROWSPB_ * C_;
    for (int e = tid; e < M_ * 64; e += 256) {
        int m = e >> 6, cc = e & 63;
        float v = sT[cc][m];
        __half h = __float2half_rn(v);
        __half md = __float2half_rn(v - __half2float(h));
        size_t rg = (size_t)q * M_ + m;
        size_t off = ((size_t)b * 2 * ROWSPB_ + rg) * C_ + cb64 * 64 + cc;
        g_A[off] = h;
        g_A[off + compStride] = md;
    }
}

__global__ __launch_bounds__(256) void convB_k(const float* __restrict__ sup) {
    const int cb64 = blockIdx.x;
    const int bj = blockIdx.y;
    const int b = bj / J_, j = bj - b * J_;
    const int tid = threadIdx.x;
    __shared__ float sT[64][101];

    const float* src = sup + ((size_t)bj * C_ + cb64 * 64) * M_;
    for (int e = tid; e < 64 * M_; e += 256)
        sT[e / M_][e % M_] = src[e];
    __syncthreads();

    const size_t compStride = (size_t)CPAD_ * C_;
    for (int e = tid; e < M_ * 64; e += 256) {
        int m = e >> 6, cc = e & 63;
        float v = sT[cc][m];
        __half h = __float2half_rn(v);
        __half md = __float2half_rn(v - __half2float(h));
        size_t rg = (size_t)j * M_ + m;
        size_t off = ((size_t)b * 2 * CPAD_ + rg) * C_ + cb64 * 64 + cc;
        g_B[off] = h;
        g_B[off + compStride] = md;
    }
}

// ---------------------------------------------------------------------------
// Main HMMA GEMM: CTA tile 128 rows x 256 cols, K_eff = 3*640 fp16.
// 8 warps (2m x 4n), warp tile 64x64 via m16n8k16. 4-stage cp.async pipeline.
// Grid: x in [0,600) swizzled as 15rb x 10cb groups for L2 reuse; z = b.
// ---------------------------------------------------------------------------
extern __shared__ char dynsm[];

__global__ __launch_bounds__(256, 1) void mma_gemm_k() {
    const int gx = blockIdx.x, b = blockIdx.z;
    const int grp = gx / 150, t150 = gx - grp * 150;
    const int cb = t150 % 10, rb = grp * 15 + t150 / 10;

    const int tid = threadIdx.x, lane = tid & 31, wid = tid >> 5;
    const int wm = wid >> 2, wn = wid & 3;
    const int l15 = lane & 15, hi = lane >> 4;

    __shared__ float sSinv[256];

    uintptr_t basep = ((uintptr_t)dynsm + 1023) & ~(uintptr_t)1023;
    const uint32_t aBuf = (uint32_t)__cvta_generic_to_shared((void*)basep);
    // per stage: A (16KB) + B (32KB)
    uint32_t aA[NSTAGE_], aB[NSTAGE_];
#pragma unroll
    for (int s = 0; s < NSTAGE_; s++) {
        aA[s] = aBuf + (uint32_t)s * 49152u;
        aB[s] = aA[s] + 16384u;
    }
    float* smSD = (float*)basep;   // epilogue D tile, stride 132 floats

    { int colg = cb * 256 + tid;
      sSinv[tid] = (colg < COLS_) ? g_sinv[b * COLS_ + colg] : 0.f; }

    // swizzled k-byte offsets per k16-step (rows are 128B)
    uint32_t kbs[4];
#pragma unroll
    for (int k = 0; k < 4; k++)
        kbs[k] = (uint32_t)((k * 32 + hi * 16) ^ ((lane & 7) * 16));
    uint32_t rowA[4], rowB[4];
#pragma unroll
    for (int mf = 0; mf < 4; mf++) rowA[mf] = (uint32_t)(wm * 64 + mf * 16 + l15) * 128u;
#pragma unroll
    for (int nfp = 0; nfp < 4; nfp++) rowB[nfp] = (uint32_t)(wn * 64 + nfp * 16 + l15) * 128u;

    float d[4][8][4];
#pragma unroll
    for (int mf = 0; mf < 4; mf++)
#pragma unroll
        for (int nf = 0; nf < 8; nf++)
#pragma unroll
            for (int r = 0; r < 4; r++) d[mf][nf][r] = 0.f;

    const char* gA = (const char*)g_A;
    const char* gB = (const char*)g_B;

    auto issue = [&](int c) {
        int seg = c / 10, cc = c - seg * 10;
        int p = c & (NSTAGE_ - 1);
        size_t baA = ((size_t)(b * 2 + c_mapA[seg]) * ROWSPB_ + rb * 128) * (C_ * 2)
                     + (size_t)cc * 128;
        size_t baB = ((size_t)(b * 2 + c_mapB[seg]) * CPAD_ + cb * 256) * (C_ * 2)
                     + (size_t)cc * 128;
#pragma unroll
        for (int i = 0; i < 4; i++) {      // A: 128 rows x 8 granules
            int g = tid + 256 * i;
            int r = g >> 3; uint32_t c16 = (uint32_t)(g & 7) * 16;
            cpa16(aA[p] + (uint32_t)r * 128 + (c16 ^ ((uint32_t)(r & 7) * 16)),
                  gA + baA + (size_t)r * (C_ * 2) + c16);
        }
#pragma unroll
        for (int i = 0; i < 8; i++) {      // B: 256 rows x 8 granules
            int g = tid + 256 * i;
            int r = g >> 3; uint32_t c16 = (uint32_t)(g & 7) * 16;
            cpa16(aB[p] + (uint32_t)r * 128 + (c16 ^ ((uint32_t)(r & 7) * 16)),
                  gB + baB + (size_t)r * (C_ * 2) + c16);
        }
        asm volatile("cp.async.commit_group;");
    };

    // prologue: 3 chunks in flight
    issue(0); issue(1); issue(2);

    for (int c = 0; c < NCHUNK_; c++) {
        if (c <= NCHUNK_ - 3)      asm volatile("cp.async.wait_group 2;");
        else if (c == NCHUNK_ - 2) asm volatile("cp.async.wait_group 1;");
        else                       asm volatile("cp.async.wait_group 0;");
        __syncthreads();

        if (c + 3 < NCHUNK_) issue(c + 3);

        const int p = c & (NSTAGE_ - 1);
#pragma unroll
        for (int ks = 0; ks < 4; ks++) {
            uint32_t afr[4][4], bfr[4][4];
#pragma unroll
            for (int mf = 0; mf < 4; mf++) ldsm4(afr[mf], aA[p] + rowA[mf] + kbs[ks]);
#pragma unroll
            for (int nfp = 0; nfp < 4; nfp++) ldsm4(bfr[nfp], aB[p] + rowB[nfp] + kbs[ks]);
#pragma unroll
            for (int mf = 0; mf < 4; mf++)
#pragma unroll
                for (int nf = 0; nf < 8; nf++)
                    hmma(d[mf][nf], afr[mf],
                         bfr[nf >> 1][nf & 1], bfr[nf >> 1][(nf & 1) + 2]);
        }
    }
    __syncthreads();   // all warps done with last stage before smem reuse

    // ---- epilogue: two 128x128 halves through smem, fused reductions ----
    float cmax[NW_];
#pragma unroll
    for (int w = 0; w < NW_; w++) cmax[w] = -FLT_MAX;
    float gv = -FLT_MAX;
    int gi = 0;

    const int rg = rb * 128 + tid;                 // reducer row (tid<128)
    const bool rvalid = (tid < 128) && (rg < Q_ * M_);
    float qiv = 0.f;
    if (rvalid) {
        int q = rg / M_, m = rg - q * M_;
        qiv = g_qinv[(b * Q_ + q) * M_ + m];
    }

#pragma unroll
    for (int h = 0; h < 2; h++) {
        __syncthreads();
        if ((wn >> 1) == h) {
#pragma unroll
            for (int mf = 0; mf < 4; mf++)
#pragma unroll
                for (int nf = 0; nf < 8; nf++) {
                    int row = wm * 64 + mf * 16 + (lane >> 2);
                    int coll = (wn & 1) * 64 + nf * 8 + (lane & 3) * 2;
                    smSD[row * 132 + coll]       = d[mf][nf][0];
                    smSD[row * 132 + coll + 1]   = d[mf][nf][1];
                    smSD[(row + 8) * 132 + coll]     = d[mf][nf][2];
                    smSD[(row + 8) * 132 + coll + 1] = d[mf][nf][3];
                }
        }
        __syncthreads();
        if (rvalid) {
            for (int cl = 0; cl < 128; cl++) {
                int colg = cb * 256 + h * 128 + cl;
                if (colg < COLS_) {
                    float v = smSD[tid * 132 + cl] * qiv * sSinv[h * 128 + cl];
                    int cls = colg / MS_;
                    if (v > cmax[cls]) cmax[cls] = v;
                    if (v > gv) { gv = v; gi = colg; }   // ascending -> first-index ties
                }
            }
        }
    }

    if (rvalid) {
        size_t pr = ((size_t)b * ROWSPB_ + rg) * CB_ + cb;
#pragma unroll
        for (int w = 0; w < NW_; w++) g_pcm[pr * NW_ + w] = cmax[w];
        g_pgv[pr] = gv;
        g_pgi[pr] = gi;
    }
}

// ---------------------------------------------------------------------------
// Merge partials + mutual-nearest mask + predict (one block per (b,q)).
// ---------------------------------------------------------------------------
__global__ __launch_bounds__(128) void mask_k() {
    const int bq = blockIdx.x;
    const int b = bq / Q_;
    const int tid = threadIdx.x;

    __shared__ float sCm[M_][NW_];
    __shared__ float sDiff[M_];
    __shared__ int   sNear[M_];
    __shared__ float sMask[M_];

    if (tid < M_) {
        int rg = (bq % Q_) * M_ + tid;
        size_t basep = ((size_t)b * ROWSPB_ + rg) * CB_;
        float cm[NW_];
#pragma unroll
        for (int w = 0; w < NW_; w++) cm[w] = -FLT_MAX;
        float gv = -FLT_MAX;
        int gi = 0;
        for (int t = 0; t < CB_; t++) {          // ascending col-block order
            size_t p = basep + t;
#pragma unroll
            for (int w = 0; w < NW_; w++) {
                float v = g_pcm[p * NW_ + w];
                if (v > cm[w]) cm[w] = v;
            }
            float v = g_pgv[p];
            if (v > gv) { gv = v; gi = g_pgi[p]; }
        }
        float m1 = -FLT_MAX, m2 = -FLT_MAX;
#pragma unroll
        for (int w = 0; w < NW_; w++) {
            float v = cm[w];
            if (v > m1) { m2 = m1; m1 = v; }
            else if (v > m2) { m2 = v; }
            sCm[tid][w] = v;
        }
        sDiff[tid] = m1 - m2;
        sNear[tid] = gi;
    }
    __syncthreads();

    if (tid < M_) {
        int slot = sNear[tid];
        float best = -1.0f;
        int idx = -1;
        for (int mp = 0; mp < M_; mp++) {
            float v = (sNear[mp] == slot) ? sDiff[mp] : 0.0f;
            if (v > best) { best = v; idx = mp; }
        }
        sMask[tid] = (idx == tid) ? TEMP_ : 0.0f;
    }
    __syncthreads();

    if (tid < NW_) {
        float p = 0.f;
        for (int m = 0; m < M_; m++)
            p += sCm[m][tid] * sMask[m];
        g_pred[bq * NW_ + tid] = p;
    }
}

// ---------------------------------------------------------------------------
// Loss: log-softmax NLL, deterministic tree reduction.
// ---------------------------------------------------------------------------
__global__ void loss_k(const int* __restrict__ qy, float* __restrict__ out) {
    __shared__ float part[512];
    int t = threadIdx.x;
    float v = 0.f;
    if (t < BQ_) {
        const float* p = g_pred + t * NW_;
        float mx = p[0];
#pragma unroll
        for (int w = 1; w < NW_; w++) mx = fmaxf(mx, p[w]);
        float se = 0.f;
#pragma unroll
        for (int w = 0; w < NW_; w++) se += expf(p[w] - mx);
        float lse = mx + logf(se);
        int y = qy[t];
        v = p[y] - lse;
    }
    part[t] = v;
    __syncthreads();
    for (int s = 256; s > 0; s >>= 1) {
        if (t < s) part[t] += part[t + s];
        __syncthreads();
    }
    if (t == 0) out[0] = -part[0] / (float)BQ_;
}

// ---------------------------------------------------------------------------
extern "C" void kernel_launch(void* const* d_in, const int* in_sizes, int n_in,
                              void* d_out, int out_size)
{
    const float* support_xf = (const float*)d_in[0];   // [4,25,640,100]
    const float* query_xf   = (const float*)d_in[2];   // [4,75,640,100]
    const int*   query_y    = (const int*)d_in[3];     // [4,75]
    float* out = (float*)d_out;

    cudaFuncSetAttribute(mma_gemm_k, cudaFuncAttributeMaxDynamicSharedMemorySize,
                         NSTAGE_ * 49152);

    qnorm_k<<<BQ_, 128>>>(query_xf);
    snorm_k<<<B_ * J_, 128>>>(support_xf);
    convA_k<<<dim3(10, BQ_), 256>>>(query_xf);
    convB_k<<<dim3(10, B_ * J_), 256>>>(support_xf);
    mma_gemm_k<<<dim3(600, 1, B_), 256, NSTAGE_ * 49152>>>();
    mask_k<<<BQ_, 128>>>();
    loss_k<<<1, 512>>>(query_y, out);
}

// round 11
// speedup vs baseline: 4.7270x; 1.0005x over previous
#include <cuda_runtime.h>
#include <cuda_fp16.h>
#include <cuda_fp8.h>
#include <math.h>
#include <float.h>
#include <stdint.h>

typedef unsigned long long ull;

// Problem constants
#define B_      4
#define Q_      75
#define BQ_     300
#define C_      640
#define M_      100
#define J_      25
#define NW_     5
#define MS_     500
#define COLS_   2500
#define ROWSPB_ 7680          // padded rows per b (7500 -> 60*128)
#define CPAD_   2560          // padded cols (2500 -> 10*256)
#define RB_     60            // row blocks of 128
#define CB_     10            // col blocks of 256
#define NCHUNK_ 20            // 10 fp8 (hm, mh) + 10 fp16 (hh)
#define NSTAGE_ 4
#define EPS_    1e-8f
#define TEMP_   2.0f
#define MSCL_   2048.0f       // 2^11 scale on m-components for e4m3 range
#define MINV_   (1.0f/2048.0f)

// Static device scratch (no allocation).
__device__ __align__(128) __half g_Ah[(size_t)B_ * ROWSPB_ * C_];          // 39.3MB fp16 h
__device__ __align__(128) __half g_Bh[(size_t)B_ * CPAD_ * C_];            // 13.1MB
__device__ __align__(128) unsigned char g_A8[(size_t)B_ * 2 * ROWSPB_ * C_]; // 39.3MB e4m3 {h8, m8*2^11}
__device__ __align__(128) unsigned char g_B8[(size_t)B_ * 2 * CPAD_ * C_];   // 13.1MB
__device__ float g_qinv[BQ_ * M_];
__device__ float g_sinv[B_ * COLS_];
__device__ float g_pcm[(size_t)B_ * ROWSPB_ * CB_ * NW_];
__device__ float g_pgv[(size_t)B_ * ROWSPB_ * CB_];
__device__ int   g_pgi[(size_t)B_ * ROWSPB_ * CB_];
__device__ float g_pred[BQ_ * NW_];

__device__ __forceinline__ void cpa16(uint32_t dst, const void* src) {
    asm volatile("cp.async.cg.shared.global [%0], [%1], 16;" :: "r"(dst), "l"(src));
}
__device__ __forceinline__ void ldsm4(uint32_t* r, uint32_t addr) {
    asm volatile("ldmatrix.sync.aligned.m8n8.x4.shared.b16 {%0,%1,%2,%3}, [%4];"
        : "=r"(r[0]), "=r"(r[1]), "=r"(r[2]), "=r"(r[3]) : "r"(addr));
}
__device__ __forceinline__ void hmma16(float* d, const uint32_t* a, uint32_t b0, uint32_t b1) {
    asm volatile("mma.sync.aligned.m16n8k16.row.col.f32.f16.f16.f32 "
        "{%0,%1,%2,%3}, {%4,%5,%6,%7}, {%8,%9}, {%0,%1,%2,%3};"
        : "+f"(d[0]), "+f"(d[1]), "+f"(d[2]), "+f"(d[3])
        : "r"(a[0]), "r"(a[1]), "r"(a[2]), "r"(a[3]), "r"(b0), "r"(b1));
}
__device__ __forceinline__ void hmma8(float* d, const uint32_t* a, uint32_t b0, uint32_t b1) {
    asm volatile("mma.sync.aligned.m16n8k32.row.col.f32.e4m3.e4m3.f32 "
        "{%0,%1,%2,%3}, {%4,%5,%6,%7}, {%8,%9}, {%0,%1,%2,%3};"
        : "+f"(d[0]), "+f"(d[1]), "+f"(d[2]), "+f"(d[3])
        : "r"(a[0]), "r"(a[1]), "r"(a[2]), "r"(a[3]), "r"(b0), "r"(b1));
}
__device__ __forceinline__ unsigned char to_e4m3(float v) {
    return (unsigned char)__nv_cvt_float_to_fp8(v, __NV_SATFINITE, __NV_E4M3);
}

// ---------------------------------------------------------------------------
// Inverse-norm kernels
// ---------------------------------------------------------------------------
__global__ void qnorm_k(const float* __restrict__ q) {
    int bq = blockIdx.x, t = threadIdx.x;
    if (t >= M_) return;
    const float* p = q + (size_t)bq * (C_ * M_) + t;
    float ss = 0.f;
#pragma unroll 8
    for (int c = 0; c < C_; c++) { float v = p[(size_t)c * M_]; ss = fmaf(v, v, ss); }
    g_qinv[bq * M_ + t] = 1.0f / (sqrtf(ss) + EPS_);
}
__global__ void snorm_k(const float* __restrict__ s) {
    int bj = blockIdx.x, t = threadIdx.x;
    if (t >= M_) return;
    const float* p = s + (size_t)bj * (C_ * M_) + t;
    float ss = 0.f;
#pragma unroll 8
    for (int c = 0; c < C_; c++) { float v = p[(size_t)c * M_]; ss = fmaf(v, v, ss); }
    int b = bj / J_, j = bj % J_;
    g_sinv[b * COLS_ + j * M_ + t] = 1.0f / (sqrtf(ss) + EPS_);
}

// ---------------------------------------------------------------------------
// Conversion: fp32 -> fp16 h (for hh) + e4m3 {h8, m8*2^11} (for hm/mh).
// k-major rows via smem transpose.
// ---------------------------------------------------------------------------
__global__ __launch_bounds__(256) void convA_k(const float* __restrict__ qry) {
    const int cb64 = blockIdx.x;           // k-block of 64 channels
    const int bq = blockIdx.y;
    const int b = bq / Q_, q = bq - b * Q_;
    const int tid = threadIdx.x;
    __shared__ float sT[64][101];

    const float* src = qry + ((size_t)bq * C_ + cb64 * 64) * M_;
    for (int e = tid; e < 64 * M_; e += 256)
        sT[e / M_][e % M_] = src[e];               // coalesced (m contiguous)
    __syncthreads();

    const size_t cs8 = (size_t)ROWSPB_ * C_;
    for (int e = tid; e < M_ * 64; e += 256) {
        int m = e >> 6, cc = e & 63;
        float v = sT[cc][m];
        __half h = __float2half_rn(v);
        float hf = __half2float(h);
        float md = v - hf;
        size_t rg = (size_t)q * M_ + m;
        size_t k = (size_t)cb64 * 64 + cc;
        g_Ah[((size_t)b * ROWSPB_ + rg) * C_ + k] = h;
        size_t o8 = ((size_t)(b * 2) * ROWSPB_ + rg) * C_ + k;
        g_A8[o8]       = to_e4m3(hf);
        g_A8[o8 + cs8] = to_e4m3(md * MSCL_);
    }
}

__global__ __launch_bounds__(256) void convB_k(const float* __restrict__ sup) {
    const int cb64 = blockIdx.x;
    const int bj = blockIdx.y;
    const int b = bj / J_, j = bj - b * J_;
    const int tid = threadIdx.x;
    __shared__ float sT[64][101];

    const float* src = sup + ((size_t)bj * C_ + cb64 * 64) * M_;
    for (int e = tid; e < 64 * M_; e += 256)
        sT[e / M_][e % M_] = src[e];
    __syncthreads();

    const size_t cs8 = (size_t)CPAD_ * C_;
    for (int e = tid; e < M_ * 64; e += 256) {
        int m = e >> 6, cc = e & 63;
        float v = sT[cc][m];
        __half h = __float2half_rn(v);
        float hf = __half2float(h);
        float md = v - hf;
        size_t rg = (size_t)j * M_ + m;
        size_t k = (size_t)cb64 * 64 + cc;
        g_Bh[((size_t)b * CPAD_ + rg) * C_ + k] = h;
        size_t o8 = ((size_t)(b * 2) * CPAD_ + rg) * C_ + k;
        g_B8[o8]       = to_e4m3(hf);
        g_B8[o8 + cs8] = to_e4m3(md * MSCL_);
    }
}

// ---------------------------------------------------------------------------
// Main MMA GEMM: CTA tile 128 rows x 256 cols.
// Phase 1 (chunks 0-9): e4m3 m16n8k32, segments hm (A_h8 x B_m8') and
//   mh (A_m8' x B_h8), k=128/chunk. Then d *= 2^-11.
// Phase 2 (chunks 10-19): fp16 m16n8k16 hh, k=64/chunk.
// 8 warps (2m x 4n), warp tile 64x64. 4-stage cp.async pipeline.
// Grid: x in [0,600) swizzled as 15rb x 10cb groups for L2 reuse; z = b.
// ---------------------------------------------------------------------------
extern __shared__ char dynsm[];

__global__ __launch_bounds__(256, 1) void mma_gemm_k() {
    const int gx = blockIdx.x, b = blockIdx.z;
    const int grp = gx / 150, t150 = gx - grp * 150;
    const int cb = t150 % 10, rb = grp * 15 + t150 / 10;

    const int tid = threadIdx.x, lane = tid & 31, wid = tid >> 5;
    const int wm = wid >> 2, wn = wid & 3;
    const int l15 = lane & 15, hi = lane >> 4;

    __shared__ float sSinv[256];

    uintptr_t basep = ((uintptr_t)dynsm + 1023) & ~(uintptr_t)1023;
    const uint32_t aBuf = (uint32_t)__cvta_generic_to_shared((void*)basep);
    uint32_t aA[NSTAGE_], aB[NSTAGE_];
#pragma unroll
    for (int s = 0; s < NSTAGE_; s++) {
        aA[s] = aBuf + (uint32_t)s * 49152u;
        aB[s] = aA[s] + 16384u;
    }
    float* smSD = (float*)basep;   // epilogue D tile, stride 132 floats

    { int colg = cb * 256 + tid;
      sSinv[tid] = (colg < COLS_) ? g_sinv[b * COLS_ + colg] : 0.f; }

    // swizzled k-byte offsets per 32B k-step (rows are 128B; same bytes for
    // fp16 k16 and e4m3 k32 atoms)
    uint32_t kbs[4];
#pragma unroll
    for (int k = 0; k < 4; k++)
        kbs[k] = (uint32_t)((k * 32 + hi * 16) ^ ((lane & 7) * 16));
    uint32_t rowA[4], rowB[4];
#pragma unroll
    for (int mf = 0; mf < 4; mf++) rowA[mf] = (uint32_t)(wm * 64 + mf * 16 + l15) * 128u;
#pragma unroll
    for (int nfp = 0; nfp < 4; nfp++) rowB[nfp] = (uint32_t)(wn * 64 + nfp * 16 + l15) * 128u;

    float d[4][8][4];
#pragma unroll
    for (int mf = 0; mf < 4; mf++)
#pragma unroll
        for (int nf = 0; nf < 8; nf++)
#pragma unroll
            for (int r = 0; r < 4; r++) d[mf][nf][r] = 0.f;

    auto issue = [&](int c) {
        int p = c & (NSTAGE_ - 1);
        const char* srcA; const char* srcB;
        size_t strA, strB;
        if (c < 10) {            // fp8 phase: seg 0 = hm, seg 1 = mh
            int seg = c / 5, cc = c - seg * 5;
            srcA = (const char*)g_A8
                 + ((size_t)(b * 2 + seg) * ROWSPB_ + (size_t)rb * 128) * C_
                 + (size_t)cc * 128;
            srcB = (const char*)g_B8
                 + ((size_t)(b * 2 + (1 - seg)) * CPAD_ + (size_t)cb * 256) * C_
                 + (size_t)cc * 128;
            strA = C_; strB = C_;
        } else {                 // fp16 hh phase
            int cc = c - 10;
            srcA = (const char*)g_Ah
                 + (((size_t)b * ROWSPB_ + (size_t)rb * 128) * C_ + (size_t)cc * 64) * 2;
            srcB = (const char*)g_Bh
                 + (((size_t)b * CPAD_ + (size_t)cb * 256) * C_ + (size_t)cc * 64) * 2;
            strA = C_ * 2; strB = C_ * 2;
        }
#pragma unroll
        for (int i = 0; i < 4; i++) {      // A: 128 rows x 8 granules of 16B
            int g = tid + 256 * i;
            int r = g >> 3; uint32_t c16 = (uint32_t)(g & 7) * 16;
            cpa16(aA[p] + (uint32_t)r * 128 + (c16 ^ ((uint32_t)(r & 7) * 16)),
                  srcA + (size_t)r * strA + c16);
        }
#pragma unroll
        for (int i = 0; i < 8; i++) {      // B: 256 rows x 8 granules of 16B
            int g = tid + 256 * i;
            int r = g >> 3; uint32_t c16 = (uint32_t)(g & 7) * 16;
            cpa16(aB[p] + (uint32_t)r * 128 + (c16 ^ ((uint32_t)(r & 7) * 16)),
                  srcB + (size_t)r * strB + c16);
        }
        asm volatile("cp.async.commit_group;");
    };

    // prologue: 3 chunks in flight
    issue(0); issue(1); issue(2);

    for (int c = 0; c < NCHUNK_; c++) {
        if (c <= NCHUNK_ - 3)      asm volatile("cp.async.wait_group 2;");
        else if (c == NCHUNK_ - 2) asm volatile("cp.async.wait_group 1;");
        else                       asm volatile("cp.async.wait_group 0;");
        __syncthreads();

        if (c + 3 < NCHUNK_) issue(c + 3);

        if (c == 10) {             // end of fp8 phase: apply 2^-11 scale once
#pragma unroll
            for (int mf = 0; mf < 4; mf++)
#pragma unroll
                for (int nf = 0; nf < 8; nf++)
#pragma unroll
                    for (int r = 0; r < 4; r++) d[mf][nf][r] *= MINV_;
        }

        const int p = c & (NSTAGE_ - 1);
        if (c < 10) {
#pragma unroll
            for (int ks = 0; ks < 4; ks++) {
                uint32_t afr[4][4], bfr[4][4];
#pragma unroll
                for (int mf = 0; mf < 4; mf++) ldsm4(afr[mf], aA[p] + rowA[mf] + kbs[ks]);
#pragma unroll
                for (int nfp = 0; nfp < 4; nfp++) ldsm4(bfr[nfp], aB[p] + rowB[nfp] + kbs[ks]);
#pragma unroll
                for (int mf = 0; mf < 4; mf++)
#pragma unroll
                    for (int nf = 0; nf < 8; nf++)
                        hmma8(d[mf][nf], afr[mf],
                              bfr[nf >> 1][nf & 1], bfr[nf >> 1][(nf & 1) + 2]);
            }
        } else {
#pragma unroll
            for (int ks = 0; ks < 4; ks++) {
                uint32_t afr[4][4], bfr[4][4];
#pragma unroll
                for (int mf = 0; mf < 4; mf++) ldsm4(afr[mf], aA[p] + rowA[mf] + kbs[ks]);
#pragma unroll
                for (int nfp = 0; nfp < 4; nfp++) ldsm4(bfr[nfp], aB[p] + rowB[nfp] + kbs[ks]);
#pragma unroll
                for (int mf = 0; mf < 4; mf++)
#pragma unroll
                    for (int nf = 0; nf < 8; nf++)
                        hmma16(d[mf][nf], afr[mf],
                               bfr[nf >> 1][nf & 1], bfr[nf >> 1][(nf & 1) + 2]);
            }
        }
    }
    __syncthreads();   // all warps done with last stage before smem reuse

    // ---- epilogue: two 128x128 halves through smem, fused reductions ----
    float cmax[NW_];
#pragma unroll
    for (int w = 0; w < NW_; w++) cmax[w] = -FLT_MAX;
    float gv = -FLT_MAX;
    int gi = 0;

    const int rg = rb * 128 + tid;                 // reducer row (tid<128)
    const bool rvalid = (tid < 128) && (rg < Q_ * M_);
    float qiv = 0.f;
    if (rvalid) {
        int q = rg / M_, m = rg - q * M_;
        qiv = g_qinv[(b * Q_ + q) * M_ + m];
    }

#pragma unroll
    for (int h = 0; h < 2; h++) {
        __syncthreads();
        if ((wn >> 1) == h) {
#pragma unroll
            for (int mf = 0; mf < 4; mf++)
#pragma unroll
                for (int nf = 0; nf < 8; nf++) {
                    int row = wm * 64 + mf * 16 + (lane >> 2);
                    int coll = (wn & 1) * 64 + nf * 8 + (lane & 3) * 2;
                    smSD[row * 132 + coll]       = d[mf][nf][0];
                    smSD[row * 132 + coll + 1]   = d[mf][nf][1];
                    smSD[(row + 8) * 132 + coll]     = d[mf][nf][2];
                    smSD[(row + 8) * 132 + coll + 1] = d[mf][nf][3];
                }
        }
        __syncthreads();
        if (rvalid) {
            for (int cl = 0; cl < 128; cl++) {
                int colg = cb * 256 + h * 128 + cl;
                if (colg < COLS_) {
                    float v = smSD[tid * 132 + cl] * qiv * sSinv[h * 128 + cl];
                    int cls = colg / MS_;
                    if (v > cmax[cls]) cmax[cls] = v;
                    if (v > gv) { gv = v; gi = colg; }   // ascending -> first-index ties
                }
            }
        }
    }

    if (rvalid) {
        size_t pr = ((size_t)b * ROWSPB_ + rg) * CB_ + cb;
#pragma unroll
        for (int w = 0; w < NW_; w++) g_pcm[pr * NW_ + w] = cmax[w];
        g_pgv[pr] = gv;
        g_pgi[pr] = gi;
    }
}

// ---------------------------------------------------------------------------
// Merge partials + mutual-nearest mask + predict (one block per (b,q)).
// ---------------------------------------------------------------------------
__global__ __launch_bounds__(128) void mask_k() {
    const int bq = blockIdx.x;
    const int b = bq / Q_;
    const int tid = threadIdx.x;

    __shared__ float sCm[M_][NW_];
    __shared__ float sDiff[M_];
    __shared__ int   sNear[M_];
    __shared__ float sMask[M_];

    if (tid < M_) {
        int rg = (bq % Q_) * M_ + tid;
        size_t basep = ((size_t)b * ROWSPB_ + rg) * CB_;
        float cm[NW_];
#pragma unroll
        for (int w = 0; w < NW_; w++) cm[w] = -FLT_MAX;
        float gv = -FLT_MAX;
        int gi = 0;
        for (int t = 0; t < CB_; t++) {          // ascending col-block order
            size_t p = basep + t;
#pragma unroll
            for (int w = 0; w < NW_; w++) {
                float v = g_pcm[p * NW_ + w];
                if (v > cm[w]) cm[w] = v;
            }
            float v = g_pgv[p];
            if (v > gv) { gv = v; gi = g_pgi[p]; }
        }
        float m1 = -FLT_MAX, m2 = -FLT_MAX;
#pragma unroll
        for (int w = 0; w < NW_; w++) {
            float v = cm[w];
            if (v > m1) { m2 = m1; m1 = v; }
            else if (v > m2) { m2 = v; }
            sCm[tid][w] = v;
        }
        sDiff[tid] = m1 - m2;
        sNear[tid] = gi;
    }
    __syncthreads();

    if (tid < M_) {
        int slot = sNear[tid];
        float best = -1.0f;
        int idx = -1;
        for (int mp = 0; mp < M_; mp++) {
            float v = (sNear[mp] == slot) ? sDiff[mp] : 0.0f;
            if (v > best) { best = v; idx = mp; }
        }
        sMask[tid] = (idx == tid) ? TEMP_ : 0.0f;
    }
    __syncthreads();

    if (tid < NW_) {
        float p = 0.f;
        for (int m = 0; m < M_; m++)
            p += sCm[m][tid] * sMask[m];
        g_pred[bq * NW_ + tid] = p;
    }
}

// ---------------------------------------------------------------------------
// Loss: log-softmax NLL, deterministic tree reduction.
// ---------------------------------------------------------------------------
__global__ void loss_k(const int* __restrict__ qy, float* __restrict__ out) {
    __shared__ float part[512];
    int t = threadIdx.x;
    float v = 0.f;
    if (t < BQ_) {
        const float* p = g_pred + t * NW_;
        float mx = p[0];
#pragma unroll
        for (int w = 1; w < NW_; w++) mx = fmaxf(mx, p[w]);
        float se = 0.f;
#pragma unroll
        for (int w = 0; w < NW_; w++) se += expf(p[w] - mx);
        float lse = mx + logf(se);
        int y = qy[t];
        v = p[y] - lse;
    }
    part[t] = v;
    __syncthreads();
    for (int s = 256; s > 0; s >>= 1) {
        if (t < s) part[t] += part[t + s];
        __syncthreads();
    }
    if (t == 0) out[0] = -part[0] / (float)BQ_;
}

// ---------------------------------------------------------------------------
extern "C" void kernel_launch(void* const* d_in, const int* in_sizes, int n_in,
                              void* d_out, int out_size)
{
    const float* support_xf = (const float*)d_in[0];   // [4,25,640,100]
    const float* query_xf   = (const float*)d_in[2];   // [4,75,640,100]
    const int*   query_y    = (const int*)d_in[3];     // [4,75]
    float* out = (float*)d_out;

    cudaFuncSetAttribute(mma_gemm_k, cudaFuncAttributeMaxDynamicSharedMemorySize,
                         NSTAGE_ * 49152);

    qnorm_k<<<BQ_, 128>>>(query_xf);
    snorm_k<<<B_ * J_, 128>>>(support_xf);
    convA_k<<<dim3(10, BQ_), 256>>>(query_xf);
    convB_k<<<dim3(10, B_ * J_), 256>>>(support_xf);
    mma_gemm_k<<<dim3(600, 1, B_), 256, NSTAGE_ * 49152>>>();
    mask_k<<<BQ_, 128>>>();
    loss_k<<<1, 512>>>(query_y, out);
}